// round 7
// baseline (speedup 1.0000x reference)
#include <cuda_runtime.h>
#include <cuda_bf16.h>
#include <cstdint>

#define Bb   4
#define Ss   4096
#define FIN  512
#define FOUT 512
#define KW   17
#define Gg   8
#define Dd   64
#define PADK 8
#define Mrows (Bb*Ss)   // 16384

__device__ float g_q[(size_t)Mrows*FOUT];
__device__ float g_k[(size_t)Mrows*FOUT];
__device__ float g_v[(size_t)Mrows*FOUT];

// bf16 hi/lo split operands (pre-pass output)
__device__ __nv_bfloat16 g_xh[(size_t)Mrows*FIN];
__device__ __nv_bfloat16 g_xl[(size_t)Mrows*FIN];
__device__ __nv_bfloat16 g_wh[3][(size_t)FOUT*FIN];
__device__ __nv_bfloat16 g_wl[3][(size_t)FOUT*FIN];

// ---------------------------------------------------------------------------
__device__ __forceinline__ void mma_bf16(float* d, const uint32_t* a,
                                         uint32_t b0, uint32_t b1) {
    asm volatile(
        "mma.sync.aligned.m16n8k16.row.col.f32.bf16.bf16.f32 "
        "{%0,%1,%2,%3}, {%4,%5,%6,%7}, {%8,%9}, {%0,%1,%2,%3};"
        : "+f"(d[0]), "+f"(d[1]), "+f"(d[2]), "+f"(d[3])
        : "r"(a[0]), "r"(a[1]), "r"(a[2]), "r"(a[3]), "r"(b0), "r"(b1));
}

__device__ __forceinline__ void cp_async16(void* smem, const void* gmem) {
    uint32_t s = (uint32_t)__cvta_generic_to_shared(smem);
    asm volatile("cp.async.cg.shared.global [%0], [%1], 16;" :: "r"(s), "l"(gmem));
}
__device__ __forceinline__ void cp_commit() { asm volatile("cp.async.commit_group;"); }
__device__ __forceinline__ void cp_wait0() { asm volatile("cp.async.wait_group 0;"); }

__device__ __forceinline__ uint64_t pack4bf(__nv_bfloat16 a, __nv_bfloat16 b,
                                            __nv_bfloat16 c, __nv_bfloat16 d) {
    return (uint64_t)__bfloat16_as_ushort(a)
         | ((uint64_t)__bfloat16_as_ushort(b) << 16)
         | ((uint64_t)__bfloat16_as_ushort(c) << 32)
         | ((uint64_t)__bfloat16_as_ushort(d) << 48);
}

// ---------------------------------------------------------------------------
// Pre-pass: split fp32 -> bf16 hi + bf16 lo (residual).
// ---------------------------------------------------------------------------
__global__ __launch_bounds__(256) void split_x(const float* __restrict__ src) {
    const size_t i = (size_t)blockIdx.x * 256 + threadIdx.x;
    float4 v = ((const float4*)src)[i];
    float a[4] = {v.x, v.y, v.z, v.w};
    __nv_bfloat16 h[4], l[4];
#pragma unroll
    for (int u = 0; u < 4; u++) {
        h[u] = __float2bfloat16(a[u]);
        l[u] = __float2bfloat16(a[u] - __bfloat162float(h[u]));
    }
    ((uint64_t*)g_xh)[i] = pack4bf(h[0], h[1], h[2], h[3]);
    ((uint64_t*)g_xl)[i] = pack4bf(l[0], l[1], l[2], l[3]);
}

__global__ __launch_bounds__(256) void split_w(const float* __restrict__ Wq,
                                               const float* __restrict__ Wk,
                                               const float* __restrict__ Wv) {
    const int z = blockIdx.z;
    const float* src = (z == 0) ? Wq : (z == 1) ? Wk : Wv;
    const size_t i = (size_t)blockIdx.x * 256 + threadIdx.x;
    float4 v = ((const float4*)src)[i];
    float a[4] = {v.x, v.y, v.z, v.w};
    __nv_bfloat16 h[4], l[4];
#pragma unroll
    for (int u = 0; u < 4; u++) {
        h[u] = __float2bfloat16(a[u]);
        l[u] = __float2bfloat16(a[u] - __bfloat162float(h[u]));
    }
    ((uint64_t*)g_wh[z])[i] = pack4bf(h[0], h[1], h[2], h[3]);
    ((uint64_t*)g_wl[z])[i] = pack4bf(l[0], l[1], l[2], l[3]);
}

// ---------------------------------------------------------------------------
// GEMM (3xBF16), R7: 2 CTAs/SM + pass-major mma schedule (dep distance 4).
// ---------------------------------------------------------------------------
__global__ __launch_bounds__(256, 2) void gemm_qkv(void) {
    const int z = blockIdx.z;
    const __nv_bfloat16* __restrict__ Wh = g_wh[z];
    const __nv_bfloat16* __restrict__ Wl = g_wl[z];
    float* __restrict__ C = (z == 0) ? g_q : (z == 1) ? g_k : g_v;

    __shared__ __nv_bfloat16 Ah[2][128 * 16];
    __shared__ __nv_bfloat16 Al[2][128 * 16];
    __shared__ __nv_bfloat16 Bh[2][128 * 16];
    __shared__ __nv_bfloat16 Bl[2][128 * 16];

    const int tid  = threadIdx.x;
    const int m0   = blockIdx.y * 128;
    const int n0   = blockIdx.x * 128;

    const int lrow = tid >> 1;
    const int lk   = (tid & 1) * 8;

    const __nv_bfloat16* agh = g_xh + (size_t)(m0 + lrow) * FIN + lk;
    const __nv_bfloat16* agl = g_xl + (size_t)(m0 + lrow) * FIN + lk;
    const __nv_bfloat16* bgh = Wh   + (size_t)(n0 + lrow) * FIN + lk;
    const __nv_bfloat16* bgl = Wl   + (size_t)(n0 + lrow) * FIN + lk;
    __nv_bfloat16* sah = &Ah[0][lrow * 16 + lk];
    __nv_bfloat16* sal = &Al[0][lrow * 16 + lk];
    __nv_bfloat16* sbh = &Bh[0][lrow * 16 + lk];
    __nv_bfloat16* sbl = &Bl[0][lrow * 16 + lk];

    const int warp = tid >> 5;
    const int lane = tid & 31;
    const int wm0  = (warp >> 1) * 32;
    const int wn0  = (warp & 1) * 64;
    const int gid  = lane >> 2;
    const int tig  = lane & 3;

    float acc[2][8][4];
#pragma unroll
    for (int mt = 0; mt < 2; mt++)
#pragma unroll
        for (int nt = 0; nt < 8; nt++)
#pragma unroll
            for (int i = 0; i < 4; i++) acc[mt][nt][i] = 0.f;

    const int NT = FIN / 16;

    cp_async16(sah, agh);
    cp_async16(sal, agl);
    cp_async16(sbh, bgh);
    cp_async16(sbl, bgl);
    cp_commit();

    for (int t = 0; t < NT; t++) {
        cp_wait0();
        __syncthreads();

        if (t + 1 < NT) {
            const int nb = (t + 1) & 1;
            const int ko = (t + 1) * 16;
            cp_async16(sah + nb * 128 * 16, agh + ko);
            cp_async16(sal + nb * 128 * 16, agl + ko);
            cp_async16(sbh + nb * 128 * 16, bgh + ko);
            cp_async16(sbl + nb * 128 * 16, bgl + ko);
            cp_commit();
        }

        const __nv_bfloat16* Abh = Ah[t & 1];
        const __nv_bfloat16* Abl = Al[t & 1];
        const __nv_bfloat16* Bbh = Bh[t & 1];
        const __nv_bfloat16* Bbl = Bl[t & 1];

        uint32_t a_h[2][4], a_l[2][4];
#pragma unroll
        for (int mt = 0; mt < 2; mt++) {
            const int r0 = wm0 + mt * 16 + gid;
            uint2 v0 = *(const uint2*)&Abh[(r0    ) * 16 + 4 * tig];
            uint2 v1 = *(const uint2*)&Abh[(r0 + 8) * 16 + 4 * tig];
            a_h[mt][0] = v0.x; a_h[mt][1] = v1.x; a_h[mt][2] = v0.y; a_h[mt][3] = v1.y;
            uint2 w0 = *(const uint2*)&Abl[(r0    ) * 16 + 4 * tig];
            uint2 w1 = *(const uint2*)&Abl[(r0 + 8) * 16 + 4 * tig];
            a_l[mt][0] = w0.x; a_l[mt][1] = w1.x; a_l[mt][2] = w0.y; a_l[mt][3] = w1.y;
        }

        // nt in pairs, pass-major: 4 independent accumulators between
        // same-acc mmas (dep distance 4 instead of 1).
#pragma unroll
        for (int ntp = 0; ntp < 4; ntp++) {
            const int nt0 = 2 * ntp, nt1 = 2 * ntp + 1;
            const int na = wn0 + nt0 * 8 + gid;
            const int nb2 = wn0 + nt1 * 8 + gid;
            uint2 bh0 = *(const uint2*)&Bbh[na  * 16 + 4 * tig];
            uint2 bh1 = *(const uint2*)&Bbh[nb2 * 16 + 4 * tig];
            uint2 bl0 = *(const uint2*)&Bbl[na  * 16 + 4 * tig];
            uint2 bl1 = *(const uint2*)&Bbl[nb2 * 16 + 4 * tig];
            // pass hh
            mma_bf16(acc[0][nt0], a_h[0], bh0.x, bh0.y);
            mma_bf16(acc[1][nt0], a_h[1], bh0.x, bh0.y);
            mma_bf16(acc[0][nt1], a_h[0], bh1.x, bh1.y);
            mma_bf16(acc[1][nt1], a_h[1], bh1.x, bh1.y);
            // pass hl
            mma_bf16(acc[0][nt0], a_h[0], bl0.x, bl0.y);
            mma_bf16(acc[1][nt0], a_h[1], bl0.x, bl0.y);
            mma_bf16(acc[0][nt1], a_h[0], bl1.x, bl1.y);
            mma_bf16(acc[1][nt1], a_h[1], bl1.x, bl1.y);
            // pass lh
            mma_bf16(acc[0][nt0], a_l[0], bh0.x, bh0.y);
            mma_bf16(acc[1][nt0], a_l[1], bh0.x, bh0.y);
            mma_bf16(acc[0][nt1], a_l[0], bh1.x, bh1.y);
            mma_bf16(acc[1][nt1], a_l[1], bh1.x, bh1.y);
        }
        __syncthreads();
    }

#pragma unroll
    for (int mt = 0; mt < 2; mt++) {
#pragma unroll
        for (int nt = 0; nt < 8; nt++) {
            const int row = m0 + wm0 + mt * 16 + gid;
            const int col = n0 + wn0 + nt * 8 + 2 * tig;
            *(float2*)&C[(size_t)row * FOUT + col] =
                make_float2(acc[mt][nt][0], acc[mt][nt][1]);
            *(float2*)&C[(size_t)(row + 8) * FOUT + col] =
                make_float2(acc[mt][nt][2], acc[mt][nt][3]);
        }
    }
}

// ---------------------------------------------------------------------------
// attn v2 (unchanged from R6)
// ---------------------------------------------------------------------------
#define TSs   64
#define RROWS 80          // TSs + KW - 1
#define KSTR  68

__global__ __launch_bounds__(256) void attn2(
    const float* __restrict__ rel,     // [FOUT, KW]
    float* __restrict__ out,           // [Mrows, FOUT]
    float* __restrict__ attn_out)      // [Mrows, Gg, KW]
{
    __shared__ float ks[RROWS * KSTR];
    __shared__ float vs[RROWS * KSTR];
    __shared__ float rt[KW * Dd];      // relT[j][d]

    const int b   = blockIdx.z;
    const int g   = blockIdx.y;
    const int s0  = blockIdx.x * TSs;
    const int tid = threadIdx.x;
    const int lane = tid & 31, warp = tid >> 5;
    const int sub  = lane >> 3;               // 0..3
    const int sidx = warp * 8 + (lane & 7);   // 0..63
    const int s    = s0 + sidx;
    const int m    = b * Ss + s;

    for (int i = tid; i < RROWS * 16; i += 256) {
        const int r = i >> 4, c = (i & 15) * 4;
        const int gr = s0 - PADK + r;
        float* kd = &ks[r * KSTR + c];
        float* vd = &vs[r * KSTR + c];
        if (gr >= 0 && gr < Ss) {
            const size_t gbase = ((size_t)(b * Ss + gr)) * FOUT + g * Dd + c;
            cp_async16(kd, &g_k[gbase]);
            cp_async16(vd, &g_v[gbase]);
        } else {
            *(float4*)kd = make_float4(0.f, 0.f, 0.f, 0.f);
            *(float4*)vd = make_float4(0.f, 0.f, 0.f, 0.f);
        }
    }
    {
        const float* rsrc = rel + (size_t)g * Dd * KW;
        for (int i = tid; i < (Dd * KW) / 4; i += 256) {
            float4 v4 = *(const float4*)(rsrc + i * 4);
            float vv[4] = {v4.x, v4.y, v4.z, v4.w};
#pragma unroll
            for (int u = 0; u < 4; u++) {
                const int f = i * 4 + u;
                const int d = f / KW, j = f % KW;
                rt[j * Dd + d] = vv[u];
            }
        }
    }
    cp_commit();
    cp_wait0();
    __syncthreads();

    float4 q4[4];
    {
        const float* qp = &g_q[(size_t)m * FOUT + g * Dd + sub * 16];
#pragma unroll
        for (int c4 = 0; c4 < 4; c4++) q4[c4] = *(const float4*)(qp + 4 * c4);
    }

    float e[KW];
#pragma unroll
    for (int j = 0; j < KW; j++) {
        const float* kr = &ks[(sidx + j) * KSTR + sub * 16];
        const float* rr = &rt[j * Dd + sub * 16];
        float a0 = 0.f, a1 = 0.f;
#pragma unroll
        for (int c4 = 0; c4 < 4; c4++) {
            float4 kv = *(const float4*)(kr + 4 * c4);
            float4 rv = *(const float4*)(rr + 4 * c4);
            a0 = fmaf(q4[c4].x, kv.x + rv.x, a0);
            a1 = fmaf(q4[c4].y, kv.y + rv.y, a1);
            a0 = fmaf(q4[c4].z, kv.z + rv.z, a0);
            a1 = fmaf(q4[c4].w, kv.w + rv.w, a1);
        }
        float acc = a0 + a1;
        acc += __shfl_xor_sync(0xffffffffu, acc, 8);
        acc += __shfl_xor_sync(0xffffffffu, acc, 16);
        e[j] = acc;
    }

    float mx = e[0];
#pragma unroll
    for (int j = 1; j < KW; j++) mx = fmaxf(mx, e[j]);
    float sum = 0.f;
#pragma unroll
    for (int j = 0; j < KW; j++) { e[j] = __expf(e[j] - mx); sum += e[j]; }
    const float inv = 1.f / sum;
#pragma unroll
    for (int j = 0; j < KW; j++) e[j] *= inv;

    {
        float* ap = &attn_out[((size_t)m * Gg + g) * KW];
#pragma unroll
        for (int u = 0; u < 4; u++) {
            const int j = sub * 4 + u;
            float val = (j == 0) ? e[0] : (j == 1) ? e[1] : (j == 2) ? e[2] :
                        (j == 3) ? e[3] : (j == 4) ? e[4] : (j == 5) ? e[5] :
                        (j == 6) ? e[6] : (j == 7) ? e[7] : (j == 8) ? e[8] :
                        (j == 9) ? e[9] : (j == 10) ? e[10] : (j == 11) ? e[11] :
                        (j == 12) ? e[12] : (j == 13) ? e[13] : (j == 14) ? e[14] : e[15];
            ap[j] = val;
        }
        if (sub == 0) ap[16] = e[16];
    }

    float4 o[4];
#pragma unroll
    for (int c4 = 0; c4 < 4; c4++) o[c4] = make_float4(0.f, 0.f, 0.f, 0.f);
#pragma unroll
    for (int j = 0; j < KW; j++) {
        const float* vr = &vs[(sidx + j) * KSTR + sub * 16];
        const float w = e[j];
#pragma unroll
        for (int c4 = 0; c4 < 4; c4++) {
            float4 vv = *(const float4*)(vr + 4 * c4);
            o[c4].x = fmaf(w, vv.x, o[c4].x);
            o[c4].y = fmaf(w, vv.y, o[c4].y);
            o[c4].z = fmaf(w, vv.z, o[c4].z);
            o[c4].w = fmaf(w, vv.w, o[c4].w);
        }
    }
    {
        float* op = &out[(size_t)m * FOUT + g * Dd + sub * 16];
#pragma unroll
        for (int c4 = 0; c4 < 4; c4++) *(float4*)(op + 4 * c4) = o[c4];
    }
}

// ---------------------------------------------------------------------------
extern "C" void kernel_launch(void* const* d_in, const int* in_sizes, int n_in,
                              void* d_out, int out_size)
{
    const float* x   = (const float*)d_in[0];
    const float* Wq  = (const float*)d_in[1];
    const float* Wk  = (const float*)d_in[2];
    const float* Wv  = (const float*)d_in[3];
    const float* rel = (const float*)d_in[4];

    float* out  = (float*)d_out;
    float* attn = out + (size_t)Mrows * FOUT;

    split_x<<<(Mrows * FIN / 4) / 256, 256>>>(x);
    split_w<<<dim3((FOUT * FIN / 4) / 256, 1, 3), 256>>>(Wq, Wk, Wv);

    dim3 gg(FOUT / 128, Mrows / 128, 3);
    gemm_qkv<<<gg, 256>>>();

    dim3 ga(Ss / TSs, Gg, Bb);
    attn2<<<ga, 256>>>(rel, out, attn);
}

// round 10
// speedup vs baseline: 1.0156x; 1.0156x over previous
#include <cuda_runtime.h>
#include <cuda_bf16.h>
#include <cstdint>

#define Bb   4
#define Ss   4096
#define FIN  512
#define FOUT 512
#define KW   17
#define Gg   8
#define Dd   64
#define PADK 8
#define Mrows (Bb*Ss)   // 16384

__device__ float g_q[(size_t)Mrows*FOUT];
__device__ float g_k[(size_t)Mrows*FOUT];
__device__ float g_v[(size_t)Mrows*FOUT];

// bf16 hi/lo split operands (q,k path)
__device__ __nv_bfloat16 g_xh[(size_t)Mrows*FIN];
__device__ __nv_bfloat16 g_xl[(size_t)Mrows*FIN];
__device__ __nv_bfloat16 g_wh[2][(size_t)FOUT*FIN];
__device__ __nv_bfloat16 g_wl[2][(size_t)FOUT*FIN];
// tf32-rounded operands (v path)
__device__ float g_xt[(size_t)Mrows*FIN];
__device__ float g_wvt[(size_t)FOUT*FIN];

// ---------------------------------------------------------------------------
__device__ __forceinline__ uint32_t f2tf32(float a) {
    uint32_t h;
    asm("cvt.rna.tf32.f32 %0, %1;" : "=r"(h) : "f"(a));
    return h;
}

__device__ __forceinline__ void mma_bf16(float* d, const uint32_t* a,
                                         uint32_t b0, uint32_t b1) {
    asm volatile(
        "mma.sync.aligned.m16n8k16.row.col.f32.bf16.bf16.f32 "
        "{%0,%1,%2,%3}, {%4,%5,%6,%7}, {%8,%9}, {%0,%1,%2,%3};"
        : "+f"(d[0]), "+f"(d[1]), "+f"(d[2]), "+f"(d[3])
        : "r"(a[0]), "r"(a[1]), "r"(a[2]), "r"(a[3]), "r"(b0), "r"(b1));
}

__device__ __forceinline__ void mma_tf32(float* d, const uint32_t* a,
                                         uint32_t b0, uint32_t b1) {
    asm volatile(
        "mma.sync.aligned.m16n8k8.row.col.f32.tf32.tf32.f32 "
        "{%0,%1,%2,%3}, {%4,%5,%6,%7}, {%8,%9}, {%0,%1,%2,%3};"
        : "+f"(d[0]), "+f"(d[1]), "+f"(d[2]), "+f"(d[3])
        : "r"(a[0]), "r"(a[1]), "r"(a[2]), "r"(a[3]), "r"(b0), "r"(b1));
}

__device__ __forceinline__ void cp_async16(void* smem, const void* gmem) {
    uint32_t s = (uint32_t)__cvta_generic_to_shared(smem);
    asm volatile("cp.async.cg.shared.global [%0], [%1], 16;" :: "r"(s), "l"(gmem));
}
__device__ __forceinline__ void cp_commit() { asm volatile("cp.async.commit_group;"); }
__device__ __forceinline__ void cp_wait0() { asm volatile("cp.async.wait_group 0;"); }

__device__ __forceinline__ uint64_t pack4bf(__nv_bfloat16 a, __nv_bfloat16 b,
                                            __nv_bfloat16 c, __nv_bfloat16 d) {
    return (uint64_t)__bfloat16_as_ushort(a)
         | ((uint64_t)__bfloat16_as_ushort(b) << 16)
         | ((uint64_t)__bfloat16_as_ushort(c) << 32)
         | ((uint64_t)__bfloat16_as_ushort(d) << 48);
}

// ---------------------------------------------------------------------------
// Pre-pass: x -> bf16 hi/lo (for q,k) AND tf32-rounded fp32 (for v).
// ---------------------------------------------------------------------------
__global__ __launch_bounds__(256) void split_x(const float* __restrict__ src) {
    const size_t i = (size_t)blockIdx.x * 256 + threadIdx.x;
    float4 v = ((const float4*)src)[i];
    float a[4] = {v.x, v.y, v.z, v.w};
    __nv_bfloat16 h[4], l[4];
    uint4 t;
#pragma unroll
    for (int u = 0; u < 4; u++) {
        h[u] = __float2bfloat16(a[u]);
        l[u] = __float2bfloat16(a[u] - __bfloat162float(h[u]));
    }
    t.x = f2tf32(a[0]); t.y = f2tf32(a[1]); t.z = f2tf32(a[2]); t.w = f2tf32(a[3]);
    ((uint64_t*)g_xh)[i] = pack4bf(h[0], h[1], h[2], h[3]);
    ((uint64_t*)g_xl)[i] = pack4bf(l[0], l[1], l[2], l[3]);
    ((uint4*)g_xt)[i] = t;
}

// z=0: Wq bf16 split, z=1: Wk bf16 split, z=2: Wv tf32 round
__global__ __launch_bounds__(256) void split_w(const float* __restrict__ Wq,
                                               const float* __restrict__ Wk,
                                               const float* __restrict__ Wv) {
    const int z = blockIdx.z;
    const float* src = (z == 0) ? Wq : (z == 1) ? Wk : Wv;
    const size_t i = (size_t)blockIdx.x * 256 + threadIdx.x;
    float4 v = ((const float4*)src)[i];
    float a[4] = {v.x, v.y, v.z, v.w};
    if (z < 2) {
        __nv_bfloat16 h[4], l[4];
#pragma unroll
        for (int u = 0; u < 4; u++) {
            h[u] = __float2bfloat16(a[u]);
            l[u] = __float2bfloat16(a[u] - __bfloat162float(h[u]));
        }
        ((uint64_t*)g_wh[z])[i] = pack4bf(h[0], h[1], h[2], h[3]);
        ((uint64_t*)g_wl[z])[i] = pack4bf(l[0], l[1], l[2], l[3]);
    } else {
        uint4 t;
        t.x = f2tf32(a[0]); t.y = f2tf32(a[1]); t.z = f2tf32(a[2]); t.w = f2tf32(a[3]);
        ((uint4*)g_wvt)[i] = t;
    }
}

// ---------------------------------------------------------------------------
// q,k GEMM (3xBF16; saturates mma.sync): z in {0,1}.
// ---------------------------------------------------------------------------
__global__ __launch_bounds__(256, 2) void gemm_qk(void) {
    const int z = blockIdx.z;
    const __nv_bfloat16* __restrict__ Wh = g_wh[z];
    const __nv_bfloat16* __restrict__ Wl = g_wl[z];
    float* __restrict__ C = (z == 0) ? g_q : g_k;

    __shared__ __nv_bfloat16 Ah[2][128 * 16];
    __shared__ __nv_bfloat16 Al[2][128 * 16];
    __shared__ __nv_bfloat16 Bh[2][128 * 16];
    __shared__ __nv_bfloat16 Bl[2][128 * 16];

    const int tid  = threadIdx.x;
    const int m0   = blockIdx.y * 128;
    const int n0   = blockIdx.x * 128;

    const int lrow = tid >> 1;
    const int lk   = (tid & 1) * 8;

    const __nv_bfloat16* agh = g_xh + (size_t)(m0 + lrow) * FIN + lk;
    const __nv_bfloat16* agl = g_xl + (size_t)(m0 + lrow) * FIN + lk;
    const __nv_bfloat16* bgh = Wh   + (size_t)(n0 + lrow) * FIN + lk;
    const __nv_bfloat16* bgl = Wl   + (size_t)(n0 + lrow) * FIN + lk;
    __nv_bfloat16* sah = &Ah[0][lrow * 16 + lk];
    __nv_bfloat16* sal = &Al[0][lrow * 16 + lk];
    __nv_bfloat16* sbh = &Bh[0][lrow * 16 + lk];
    __nv_bfloat16* sbl = &Bl[0][lrow * 16 + lk];

    const int warp = tid >> 5;
    const int lane = tid & 31;
    const int wm0  = (warp >> 1) * 32;
    const int wn0  = (warp & 1) * 64;
    const int gid  = lane >> 2;
    const int tig  = lane & 3;

    float acc[2][8][4];
#pragma unroll
    for (int mt = 0; mt < 2; mt++)
#pragma unroll
        for (int nt = 0; nt < 8; nt++)
#pragma unroll
            for (int i = 0; i < 4; i++) acc[mt][nt][i] = 0.f;

    const int NT = FIN / 16;

    cp_async16(sah, agh);
    cp_async16(sal, agl);
    cp_async16(sbh, bgh);
    cp_async16(sbl, bgl);
    cp_commit();

    for (int t = 0; t < NT; t++) {
        cp_wait0();
        __syncthreads();

        if (t + 1 < NT) {
            const int nb = (t + 1) & 1;
            const int ko = (t + 1) * 16;
            cp_async16(sah + nb * 128 * 16, agh + ko);
            cp_async16(sal + nb * 128 * 16, agl + ko);
            cp_async16(sbh + nb * 128 * 16, bgh + ko);
            cp_async16(sbl + nb * 128 * 16, bgl + ko);
            cp_commit();
        }

        const __nv_bfloat16* Abh = Ah[t & 1];
        const __nv_bfloat16* Abl = Al[t & 1];
        const __nv_bfloat16* Bbh = Bh[t & 1];
        const __nv_bfloat16* Bbl = Bl[t & 1];

        uint32_t a_h[2][4], a_l[2][4];
#pragma unroll
        for (int mt = 0; mt < 2; mt++) {
            const int r0 = wm0 + mt * 16 + gid;
            uint2 v0 = *(const uint2*)&Abh[(r0    ) * 16 + 4 * tig];
            uint2 v1 = *(const uint2*)&Abh[(r0 + 8) * 16 + 4 * tig];
            a_h[mt][0] = v0.x; a_h[mt][1] = v1.x; a_h[mt][2] = v0.y; a_h[mt][3] = v1.y;
            uint2 w0 = *(const uint2*)&Abl[(r0    ) * 16 + 4 * tig];
            uint2 w1 = *(const uint2*)&Abl[(r0 + 8) * 16 + 4 * tig];
            a_l[mt][0] = w0.x; a_l[mt][1] = w1.x; a_l[mt][2] = w0.y; a_l[mt][3] = w1.y;
        }

#pragma unroll
        for (int nt = 0; nt < 8; nt++) {
            const int n = wn0 + nt * 8 + gid;
            uint2 vbh = *(const uint2*)&Bbh[n * 16 + 4 * tig];
            uint2 vbl = *(const uint2*)&Bbl[n * 16 + 4 * tig];
#pragma unroll
            for (int mt = 0; mt < 2; mt++) {
                mma_bf16(acc[mt][nt], a_h[mt], vbh.x, vbh.y);
                mma_bf16(acc[mt][nt], a_h[mt], vbl.x, vbl.y);
                mma_bf16(acc[mt][nt], a_l[mt], vbh.x, vbh.y);
            }
        }
        __syncthreads();
    }

#pragma unroll
    for (int mt = 0; mt < 2; mt++) {
#pragma unroll
        for (int nt = 0; nt < 8; nt++) {
            const int row = m0 + wm0 + mt * 16 + gid;
            const int col = n0 + wn0 + nt * 8 + 2 * tig;
            *(float2*)&C[(size_t)row * FOUT + col] =
                make_float2(acc[mt][nt][0], acc[mt][nt][1]);
            *(float2*)&C[(size_t)(row + 8) * FOUT + col] =
                make_float2(acc[mt][nt][2], acc[mt][nt][3]);
        }
    }
}

// ---------------------------------------------------------------------------
// v GEMM: single-pass TF32 (v feeds output through convex weights -> ~2e-4 ok)
// ---------------------------------------------------------------------------
__global__ __launch_bounds__(256) void gemm_v(void) {
    const float* __restrict__ W = g_wvt;
    float* __restrict__ C = g_v;

    __shared__ float As[2][128 * 16];
    __shared__ float Bs[2][128 * 16];

    const int tid  = threadIdx.x;
    const int m0   = blockIdx.y * 128;
    const int n0   = blockIdx.x * 128;

    const int lrow = tid >> 1;
    const int lk   = (tid & 1) * 8;

    const float* agp = g_xt + (size_t)(m0 + lrow) * FIN + lk;
    const float* bgp = W    + (size_t)(n0 + lrow) * FIN + lk;
    float* asp = &As[0][lrow * 16 + lk];
    float* bsp = &Bs[0][lrow * 16 + lk];

    const int warp = tid >> 5;
    const int lane = tid & 31;
    const int wm0  = (warp >> 1) * 32;
    const int wn0  = (warp & 1) * 64;
    const int gid  = lane >> 2;
    const int tig  = lane & 3;

    float acc[2][8][4];
#pragma unroll
    for (int mt = 0; mt < 2; mt++)
#pragma unroll
        for (int nt = 0; nt < 8; nt++)
#pragma unroll
            for (int i = 0; i < 4; i++) acc[mt][nt][i] = 0.f;

    const int NT = FIN / 16;

    cp_async16(asp,     agp);
    cp_async16(asp + 4, agp + 4);
    cp_async16(bsp,     bgp);
    cp_async16(bsp + 4, bgp + 4);
    cp_commit();

    for (int t = 0; t < NT; t++) {
        cp_wait0();
        __syncthreads();

        if (t + 1 < NT) {
            const int nb = (t + 1) & 1;
            const int ko = (t + 1) * 16;
            cp_async16(asp + nb * 128 * 16,     agp + ko);
            cp_async16(asp + nb * 128 * 16 + 4, agp + ko + 4);
            cp_async16(bsp + nb * 128 * 16,     bgp + ko);
            cp_async16(bsp + nb * 128 * 16 + 4, bgp + ko + 4);
            cp_commit();
        }

        const float* Ab = As[t & 1];
        const float* Bbuf = Bs[t & 1];

        uint4 va[2][2];
#pragma unroll
        for (int mt = 0; mt < 2; mt++) {
            const int r0 = wm0 + mt * 16 + gid;
            va[mt][0] = *(const uint4*)&Ab[(r0    ) * 16 + 4 * tig];
            va[mt][1] = *(const uint4*)&Ab[(r0 + 8) * 16 + 4 * tig];
        }
        uint32_t a0[2][4], a1[2][4];
#pragma unroll
        for (int mt = 0; mt < 2; mt++) {
            a0[mt][0] = va[mt][0].x; a0[mt][1] = va[mt][1].x;
            a0[mt][2] = va[mt][0].y; a0[mt][3] = va[mt][1].y;
            a1[mt][0] = va[mt][0].z; a1[mt][1] = va[mt][1].z;
            a1[mt][2] = va[mt][0].w; a1[mt][3] = va[mt][1].w;
        }

#pragma unroll
        for (int nt = 0; nt < 8; nt++) {
            const int n = wn0 + nt * 8 + gid;
            uint4 vb = *(const uint4*)&Bbuf[n * 16 + 4 * tig];
#pragma unroll
            for (int mt = 0; mt < 2; mt++) {
                mma_tf32(acc[mt][nt], a0[mt], vb.x, vb.y);
                mma_tf32(acc[mt][nt], a1[mt], vb.z, vb.w);
            }
        }
        __syncthreads();
    }

#pragma unroll
    for (int mt = 0; mt < 2; mt++) {
#pragma unroll
        for (int nt = 0; nt < 8; nt++) {
            const int row = m0 + wm0 + mt * 16 + gid;
            const int col = n0 + wn0 + nt * 8 + 2 * tig;
            *(float2*)&C[(size_t)row * FOUT + col] =
                make_float2(acc[mt][nt][0], acc[mt][nt][1]);
            *(float2*)&C[(size_t)(row + 8) * FOUT + col] =
                make_float2(acc[mt][nt][2], acc[mt][nt][3]);
        }
    }
}

// ---------------------------------------------------------------------------
// attn v3: same algorithm; __launch_bounds__(256,4) -> <=64 regs, occ 50%.
// ---------------------------------------------------------------------------
#define TSs   64
#define RROWS 80          // TSs + KW - 1
#define KSTR  68

__global__ __launch_bounds__(256, 4) void attn2(
    const float* __restrict__ rel,     // [FOUT, KW]
    float* __restrict__ out,           // [Mrows, FOUT]
    float* __restrict__ attn_out)      // [Mrows, Gg, KW]
{
    __shared__ float ks[RROWS * KSTR];
    __shared__ float vs[RROWS * KSTR];
    __shared__ float rt[KW * Dd];      // relT[j][d]

    const int b   = blockIdx.z;
    const int g   = blockIdx.y;
    const int s0  = blockIdx.x * TSs;
    const int tid = threadIdx.x;
    const int lane = tid & 31, warp = tid >> 5;
    const int sub  = lane >> 3;               // 0..3
    const int sidx = warp * 8 + (lane & 7);   // 0..63
    const int s    = s0 + sidx;
    const int m    = b * Ss + s;

    for (int i = tid; i < RROWS * 16; i += 256) {
        const int r = i >> 4, c = (i & 15) * 4;
        const int gr = s0 - PADK + r;
        float* kd = &ks[r * KSTR + c];
        float* vd = &vs[r * KSTR + c];
        if (gr >= 0 && gr < Ss) {
            const size_t gbase = ((size_t)(b * Ss + gr)) * FOUT + g * Dd + c;
            cp_async16(kd, &g_k[gbase]);
            cp_async16(vd, &g_v[gbase]);
        } else {
            *(float4*)kd = make_float4(0.f, 0.f, 0.f, 0.f);
            *(float4*)vd = make_float4(0.f, 0.f, 0.f, 0.f);
        }
    }
    {
        const float* rsrc = rel + (size_t)g * Dd * KW;
        for (int i = tid; i < (Dd * KW) / 4; i += 256) {
            float4 v4 = *(const float4*)(rsrc + i * 4);
            float vv[4] = {v4.x, v4.y, v4.z, v4.w};
#pragma unroll
            for (int u = 0; u < 4; u++) {
                const int f = i * 4 + u;
                const int d = f / KW, j = f % KW;
                rt[j * Dd + d] = vv[u];
            }
        }
    }
    cp_commit();
    cp_wait0();
    __syncthreads();

    float4 q4[4];
    {
        const float* qp = &g_q[(size_t)m * FOUT + g * Dd + sub * 16];
#pragma unroll
        for (int c4 = 0; c4 < 4; c4++) q4[c4] = *(const float4*)(qp + 4 * c4);
    }

    float e[KW];
#pragma unroll
    for (int j = 0; j < KW; j++) {
        const float* kr = &ks[(sidx + j) * KSTR + sub * 16];
        const float* rr = &rt[j * Dd + sub * 16];
        float a0 = 0.f, a1 = 0.f;
#pragma unroll
        for (int c4 = 0; c4 < 4; c4++) {
            float4 kv = *(const float4*)(kr + 4 * c4);
            float4 rv = *(const float4*)(rr + 4 * c4);
            a0 = fmaf(q4[c4].x, kv.x + rv.x, a0);
            a1 = fmaf(q4[c4].y, kv.y + rv.y, a1);
            a0 = fmaf(q4[c4].z, kv.z + rv.z, a0);
            a1 = fmaf(q4[c4].w, kv.w + rv.w, a1);
        }
        float acc = a0 + a1;
        acc += __shfl_xor_sync(0xffffffffu, acc, 8);
        acc += __shfl_xor_sync(0xffffffffu, acc, 16);
        e[j] = acc;
    }

    float mx = e[0];
#pragma unroll
    for (int j = 1; j < KW; j++) mx = fmaxf(mx, e[j]);
    float sum = 0.f;
#pragma unroll
    for (int j = 0; j < KW; j++) { e[j] = __expf(e[j] - mx); sum += e[j]; }
    const float inv = 1.f / sum;
#pragma unroll
    for (int j = 0; j < KW; j++) e[j] *= inv;

    {
        float* ap = &attn_out[((size_t)m * Gg + g) * KW];
#pragma unroll
        for (int u = 0; u < 4; u++) {
            const int j = sub * 4 + u;
            float val = (j == 0) ? e[0] : (j == 1) ? e[1] : (j == 2) ? e[2] :
                        (j == 3) ? e[3] : (j == 4) ? e[4] : (j == 5) ? e[5] :
                        (j == 6) ? e[6] : (j == 7) ? e[7] : (j == 8) ? e[8] :
                        (j == 9) ? e[9] : (j == 10) ? e[10] : (j == 11) ? e[11] :
                        (j == 12) ? e[12] : (j == 13) ? e[13] : (j == 14) ? e[14] : e[15];
            ap[j] = val;
        }
        if (sub == 0) ap[16] = e[16];
    }

    float4 o[4];
#pragma unroll
    for (int c4 = 0; c4 < 4; c4++) o[c4] = make_float4(0.f, 0.f, 0.f, 0.f);
#pragma unroll
    for (int j = 0; j < KW; j++) {
        const float* vr = &vs[(sidx + j) * KSTR + sub * 16];
        const float w = e[j];
#pragma unroll
        for (int c4 = 0; c4 < 4; c4++) {
            float4 vv = *(const float4*)(vr + 4 * c4);
            o[c4].x = fmaf(w, vv.x, o[c4].x);
            o[c4].y = fmaf(w, vv.y, o[c4].y);
            o[c4].z = fmaf(w, vv.z, o[c4].z);
            o[c4].w = fmaf(w, vv.w, o[c4].w);
        }
    }
    {
        float* op = &out[(size_t)m * FOUT + g * Dd + sub * 16];
#pragma unroll
        for (int c4 = 0; c4 < 4; c4++) *(float4*)(op + 4 * c4) = o[c4];
    }
}

// ---------------------------------------------------------------------------
extern "C" void kernel_launch(void* const* d_in, const int* in_sizes, int n_in,
                              void* d_out, int out_size)
{
    const float* x   = (const float*)d_in[0];
    const float* Wq  = (const float*)d_in[1];
    const float* Wk  = (const float*)d_in[2];
    const float* Wv  = (const float*)d_in[3];
    const float* rel = (const float*)d_in[4];

    float* out  = (float*)d_out;
    float* attn = out + (size_t)Mrows * FOUT;

    split_x<<<(Mrows * FIN / 4) / 256, 256>>>(x);
    split_w<<<dim3((FOUT * FIN / 4) / 256, 1, 3), 256>>>(Wq, Wk, Wv);

    dim3 gqk(FOUT / 128, Mrows / 128, 2);
    gemm_qk<<<gqk, 256>>>();
    dim3 gv(FOUT / 128, Mrows / 128, 1);
    gemm_v<<<gv, 256>>>();

    dim3 ga(Ss / TSs, Gg, Bb);
    attn2<<<ga, 256>>>(rel, out, attn);
}

// round 11
// speedup vs baseline: 1.0655x; 1.0492x over previous
#include <cuda_runtime.h>
#include <cuda_bf16.h>
#include <cstdint>

#define Bb   4
#define Ss   4096
#define FIN  512
#define FOUT 512
#define KW   17
#define Gg   8
#define Dd   64
#define PADK 8
#define Mrows (Bb*Ss)   // 16384

__device__ float g_q[(size_t)Mrows*FOUT];
__device__ float g_k[(size_t)Mrows*FOUT];
__device__ float g_v[(size_t)Mrows*FOUT];

// bf16 hi/lo split operands (q,k path)
__device__ __nv_bfloat16 g_xh[(size_t)Mrows*FIN];
__device__ __nv_bfloat16 g_xl[(size_t)Mrows*FIN];
__device__ __nv_bfloat16 g_wh[2][(size_t)FOUT*FIN];
__device__ __nv_bfloat16 g_wl[2][(size_t)FOUT*FIN];
// tf32-rounded operands (v path)
__device__ float g_xt[(size_t)Mrows*FIN];
__device__ float g_wvt[(size_t)FOUT*FIN];

// ---------------------------------------------------------------------------
__device__ __forceinline__ uint32_t f2tf32(float a) {
    uint32_t h;
    asm("cvt.rna.tf32.f32 %0, %1;" : "=r"(h) : "f"(a));
    return h;
}

__device__ __forceinline__ void mma_bf16(float* d, const uint32_t* a,
                                         uint32_t b0, uint32_t b1) {
    asm volatile(
        "mma.sync.aligned.m16n8k16.row.col.f32.bf16.bf16.f32 "
        "{%0,%1,%2,%3}, {%4,%5,%6,%7}, {%8,%9}, {%0,%1,%2,%3};"
        : "+f"(d[0]), "+f"(d[1]), "+f"(d[2]), "+f"(d[3])
        : "r"(a[0]), "r"(a[1]), "r"(a[2]), "r"(a[3]), "r"(b0), "r"(b1));
}

__device__ __forceinline__ void mma_tf32(float* d, const uint32_t* a,
                                         uint32_t b0, uint32_t b1) {
    asm volatile(
        "mma.sync.aligned.m16n8k8.row.col.f32.tf32.tf32.f32 "
        "{%0,%1,%2,%3}, {%4,%5,%6,%7}, {%8,%9}, {%0,%1,%2,%3};"
        : "+f"(d[0]), "+f"(d[1]), "+f"(d[2]), "+f"(d[3])
        : "r"(a[0]), "r"(a[1]), "r"(a[2]), "r"(a[3]), "r"(b0), "r"(b1));
}

__device__ __forceinline__ void cp_async16(void* smem, const void* gmem) {
    uint32_t s = (uint32_t)__cvta_generic_to_shared(smem);
    asm volatile("cp.async.cg.shared.global [%0], [%1], 16;" :: "r"(s), "l"(gmem));
}
__device__ __forceinline__ void cp_commit() { asm volatile("cp.async.commit_group;"); }
__device__ __forceinline__ void cp_wait0() { asm volatile("cp.async.wait_group 0;"); }

__device__ __forceinline__ uint64_t pack4bf(__nv_bfloat16 a, __nv_bfloat16 b,
                                            __nv_bfloat16 c, __nv_bfloat16 d) {
    return (uint64_t)__bfloat16_as_ushort(a)
         | ((uint64_t)__bfloat16_as_ushort(b) << 16)
         | ((uint64_t)__bfloat16_as_ushort(c) << 32)
         | ((uint64_t)__bfloat16_as_ushort(d) << 48);
}

// ---------------------------------------------------------------------------
// Pre-pass: x -> bf16 hi/lo (q,k) AND tf32-rounded fp32 (v).
// ---------------------------------------------------------------------------
__global__ __launch_bounds__(256) void split_x(const float* __restrict__ src) {
    const size_t i = (size_t)blockIdx.x * 256 + threadIdx.x;
    float4 v = ((const float4*)src)[i];
    float a[4] = {v.x, v.y, v.z, v.w};
    __nv_bfloat16 h[4], l[4];
    uint4 t;
#pragma unroll
    for (int u = 0; u < 4; u++) {
        h[u] = __float2bfloat16(a[u]);
        l[u] = __float2bfloat16(a[u] - __bfloat162float(h[u]));
    }
    t.x = f2tf32(a[0]); t.y = f2tf32(a[1]); t.z = f2tf32(a[2]); t.w = f2tf32(a[3]);
    ((uint64_t*)g_xh)[i] = pack4bf(h[0], h[1], h[2], h[3]);
    ((uint64_t*)g_xl)[i] = pack4bf(l[0], l[1], l[2], l[3]);
    ((uint4*)g_xt)[i] = t;
}

// z=0: Wq bf16 split, z=1: Wk bf16 split, z=2: Wv tf32 round
__global__ __launch_bounds__(256) void split_w(const float* __restrict__ Wq,
                                               const float* __restrict__ Wk,
                                               const float* __restrict__ Wv) {
    const int z = blockIdx.z;
    const float* src = (z == 0) ? Wq : (z == 1) ? Wk : Wv;
    const size_t i = (size_t)blockIdx.x * 256 + threadIdx.x;
    float4 v = ((const float4*)src)[i];
    float a[4] = {v.x, v.y, v.z, v.w};
    if (z < 2) {
        __nv_bfloat16 h[4], l[4];
#pragma unroll
        for (int u = 0; u < 4; u++) {
            h[u] = __float2bfloat16(a[u]);
            l[u] = __float2bfloat16(a[u] - __bfloat162float(h[u]));
        }
        ((uint64_t*)g_wh[z])[i] = pack4bf(h[0], h[1], h[2], h[3]);
        ((uint64_t*)g_wl[z])[i] = pack4bf(l[0], l[1], l[2], l[3]);
    } else {
        uint4 t;
        t.x = f2tf32(a[0]); t.y = f2tf32(a[1]); t.z = f2tf32(a[2]); t.w = f2tf32(a[3]);
        ((uint4*)g_wvt)[i] = t;
    }
}

// ---------------------------------------------------------------------------
// Unified GEMM: z in {0,1} -> 3xBF16 (q,k); z==2 -> single-pass TF32 (v).
// One 1536-CTA launch; both paths share one 32 KB smem union -> 2 CTAs/SM.
// ---------------------------------------------------------------------------
__global__ __launch_bounds__(256, 2) void gemm_all(void) {
    __shared__ __align__(16) char sm_u[32768];

    const int z    = blockIdx.z;
    const int tid  = threadIdx.x;
    const int m0   = blockIdx.y * 128;
    const int n0   = blockIdx.x * 128;

    const int lrow = tid >> 1;
    const int lk   = (tid & 1) * 8;

    const int warp = tid >> 5;
    const int lane = tid & 31;
    const int wm0  = (warp >> 1) * 32;
    const int wn0  = (warp & 1) * 64;
    const int gid  = lane >> 2;
    const int tig  = lane & 3;

    float acc[2][8][4];
#pragma unroll
    for (int mt = 0; mt < 2; mt++)
#pragma unroll
        for (int nt = 0; nt < 8; nt++)
#pragma unroll
            for (int i = 0; i < 4; i++) acc[mt][nt][i] = 0.f;

    const int NT = FIN / 16;

    if (z < 2) {
        // ---------------- bf16 3x path (q, k) ----------------
        __nv_bfloat16* Ah = (__nv_bfloat16*)(sm_u);          // [2][2048]
        __nv_bfloat16* Al = (__nv_bfloat16*)(sm_u + 8192);
        __nv_bfloat16* Bh = (__nv_bfloat16*)(sm_u + 16384);
        __nv_bfloat16* Bl = (__nv_bfloat16*)(sm_u + 24576);

        const __nv_bfloat16* __restrict__ Wh = g_wh[z];
        const __nv_bfloat16* __restrict__ Wl = g_wl[z];
        float* __restrict__ C = (z == 0) ? g_q : g_k;

        const __nv_bfloat16* agh = g_xh + (size_t)(m0 + lrow) * FIN + lk;
        const __nv_bfloat16* agl = g_xl + (size_t)(m0 + lrow) * FIN + lk;
        const __nv_bfloat16* bgh = Wh   + (size_t)(n0 + lrow) * FIN + lk;
        const __nv_bfloat16* bgl = Wl   + (size_t)(n0 + lrow) * FIN + lk;
        __nv_bfloat16* sah = Ah + lrow * 16 + lk;
        __nv_bfloat16* sal = Al + lrow * 16 + lk;
        __nv_bfloat16* sbh = Bh + lrow * 16 + lk;
        __nv_bfloat16* sbl = Bl + lrow * 16 + lk;

        cp_async16(sah, agh);
        cp_async16(sal, agl);
        cp_async16(sbh, bgh);
        cp_async16(sbl, bgl);
        cp_commit();

        for (int t = 0; t < NT; t++) {
            cp_wait0();
            __syncthreads();

            if (t + 1 < NT) {
                const int nb = (t + 1) & 1;
                const int ko = (t + 1) * 16;
                cp_async16(sah + nb * 2048, agh + ko);
                cp_async16(sal + nb * 2048, agl + ko);
                cp_async16(sbh + nb * 2048, bgh + ko);
                cp_async16(sbl + nb * 2048, bgl + ko);
                cp_commit();
            }

            const __nv_bfloat16* Abh = Ah + (t & 1) * 2048;
            const __nv_bfloat16* Abl = Al + (t & 1) * 2048;
            const __nv_bfloat16* Bbh = Bh + (t & 1) * 2048;
            const __nv_bfloat16* Bbl = Bl + (t & 1) * 2048;

            uint32_t a_h[2][4], a_l[2][4];
#pragma unroll
            for (int mt = 0; mt < 2; mt++) {
                const int r0 = wm0 + mt * 16 + gid;
                uint2 v0 = *(const uint2*)&Abh[(r0    ) * 16 + 4 * tig];
                uint2 v1 = *(const uint2*)&Abh[(r0 + 8) * 16 + 4 * tig];
                a_h[mt][0] = v0.x; a_h[mt][1] = v1.x; a_h[mt][2] = v0.y; a_h[mt][3] = v1.y;
                uint2 w0 = *(const uint2*)&Abl[(r0    ) * 16 + 4 * tig];
                uint2 w1 = *(const uint2*)&Abl[(r0 + 8) * 16 + 4 * tig];
                a_l[mt][0] = w0.x; a_l[mt][1] = w1.x; a_l[mt][2] = w0.y; a_l[mt][3] = w1.y;
            }

#pragma unroll
            for (int nt = 0; nt < 8; nt++) {
                const int n = wn0 + nt * 8 + gid;
                uint2 vbh = *(const uint2*)&Bbh[n * 16 + 4 * tig];
                uint2 vbl = *(const uint2*)&Bbl[n * 16 + 4 * tig];
#pragma unroll
                for (int mt = 0; mt < 2; mt++) {
                    mma_bf16(acc[mt][nt], a_h[mt], vbh.x, vbh.y);
                    mma_bf16(acc[mt][nt], a_h[mt], vbl.x, vbl.y);
                    mma_bf16(acc[mt][nt], a_l[mt], vbh.x, vbh.y);
                }
            }
            __syncthreads();
        }

#pragma unroll
        for (int mt = 0; mt < 2; mt++) {
#pragma unroll
            for (int nt = 0; nt < 8; nt++) {
                const int row = m0 + wm0 + mt * 16 + gid;
                const int col = n0 + wn0 + nt * 8 + 2 * tig;
                *(float2*)&C[(size_t)row * FOUT + col] =
                    make_float2(acc[mt][nt][0], acc[mt][nt][1]);
                *(float2*)&C[(size_t)(row + 8) * FOUT + col] =
                    make_float2(acc[mt][nt][2], acc[mt][nt][3]);
            }
        }
    } else {
        // ---------------- tf32 single-pass path (v) ----------------
        float* As = (float*)(sm_u);            // [2][2048]
        float* Bs = (float*)(sm_u + 16384);

        const float* agp = g_xt  + (size_t)(m0 + lrow) * FIN + lk;
        const float* bgp = g_wvt + (size_t)(n0 + lrow) * FIN + lk;
        float* asp = As + lrow * 16 + lk;
        float* bsp = Bs + lrow * 16 + lk;

        cp_async16(asp,     agp);
        cp_async16(asp + 4, agp + 4);
        cp_async16(bsp,     bgp);
        cp_async16(bsp + 4, bgp + 4);
        cp_commit();

        for (int t = 0; t < NT; t++) {
            cp_wait0();
            __syncthreads();

            if (t + 1 < NT) {
                const int nb = (t + 1) & 1;
                const int ko = (t + 1) * 16;
                cp_async16(asp + nb * 2048,     agp + ko);
                cp_async16(asp + nb * 2048 + 4, agp + ko + 4);
                cp_async16(bsp + nb * 2048,     bgp + ko);
                cp_async16(bsp + nb * 2048 + 4, bgp + ko + 4);
                cp_commit();
            }

            const float* Ab   = As + (t & 1) * 2048;
            const float* Bbuf = Bs + (t & 1) * 2048;

            uint4 va[2][2];
#pragma unroll
            for (int mt = 0; mt < 2; mt++) {
                const int r0 = wm0 + mt * 16 + gid;
                va[mt][0] = *(const uint4*)&Ab[(r0    ) * 16 + 4 * tig];
                va[mt][1] = *(const uint4*)&Ab[(r0 + 8) * 16 + 4 * tig];
            }
            uint32_t a0[2][4], a1[2][4];
#pragma unroll
            for (int mt = 0; mt < 2; mt++) {
                a0[mt][0] = va[mt][0].x; a0[mt][1] = va[mt][1].x;
                a0[mt][2] = va[mt][0].y; a0[mt][3] = va[mt][1].y;
                a1[mt][0] = va[mt][0].z; a1[mt][1] = va[mt][1].z;
                a1[mt][2] = va[mt][0].w; a1[mt][3] = va[mt][1].w;
            }

#pragma unroll
            for (int nt = 0; nt < 8; nt++) {
                const int n = wn0 + nt * 8 + gid;
                uint4 vb = *(const uint4*)&Bbuf[n * 16 + 4 * tig];
#pragma unroll
                for (int mt = 0; mt < 2; mt++) {
                    mma_tf32(acc[mt][nt], a0[mt], vb.x, vb.y);
                    mma_tf32(acc[mt][nt], a1[mt], vb.z, vb.w);
                }
            }
            __syncthreads();
        }

#pragma unroll
        for (int mt = 0; mt < 2; mt++) {
#pragma unroll
            for (int nt = 0; nt < 8; nt++) {
                const int row = m0 + wm0 + mt * 16 + gid;
                const int col = n0 + wn0 + nt * 8 + 2 * tig;
                *(float2*)&g_v[(size_t)row * FOUT + col] =
                    make_float2(acc[mt][nt][0], acc[mt][nt][1]);
                *(float2*)&g_v[(size_t)(row + 8) * FOUT + col] =
                    make_float2(acc[mt][nt][2], acc[mt][nt][3]);
            }
        }
    }
}

// ---------------------------------------------------------------------------
// attn (unchanged from R10): block = (b, g, 64 s), occ hint 4 CTAs/SM.
// ---------------------------------------------------------------------------
#define TSs   64
#define RROWS 80          // TSs + KW - 1
#define KSTR  68

__global__ __launch_bounds__(256, 4) void attn2(
    const float* __restrict__ rel,     // [FOUT, KW]
    float* __restrict__ out,           // [Mrows, FOUT]
    float* __restrict__ attn_out)      // [Mrows, Gg, KW]
{
    __shared__ float ks[RROWS * KSTR];
    __shared__ float vs[RROWS * KSTR];
    __shared__ float rt[KW * Dd];      // relT[j][d]

    const int b   = blockIdx.z;
    const int g   = blockIdx.y;
    const int s0  = blockIdx.x * TSs;
    const int tid = threadIdx.x;
    const int lane = tid & 31, warp = tid >> 5;
    const int sub  = lane >> 3;               // 0..3
    const int sidx = warp * 8 + (lane & 7);   // 0..63
    const int s    = s0 + sidx;
    const int m    = b * Ss + s;

    for (int i = tid; i < RROWS * 16; i += 256) {
        const int r = i >> 4, c = (i & 15) * 4;
        const int gr = s0 - PADK + r;
        float* kd = &ks[r * KSTR + c];
        float* vd = &vs[r * KSTR + c];
        if (gr >= 0 && gr < Ss) {
            const size_t gbase = ((size_t)(b * Ss + gr)) * FOUT + g * Dd + c;
            cp_async16(kd, &g_k[gbase]);
            cp_async16(vd, &g_v[gbase]);
        } else {
            *(float4*)kd = make_float4(0.f, 0.f, 0.f, 0.f);
            *(float4*)vd = make_float4(0.f, 0.f, 0.f, 0.f);
        }
    }
    {
        const float* rsrc = rel + (size_t)g * Dd * KW;
        for (int i = tid; i < (Dd * KW) / 4; i += 256) {
            float4 v4 = *(const float4*)(rsrc + i * 4);
            float vv[4] = {v4.x, v4.y, v4.z, v4.w};
#pragma unroll
            for (int u = 0; u < 4; u++) {
                const int f = i * 4 + u;
                const int d = f / KW, j = f % KW;
                rt[j * Dd + d] = vv[u];
            }
        }
    }
    cp_commit();
    cp_wait0();
    __syncthreads();

    float4 q4[4];
    {
        const float* qp = &g_q[(size_t)m * FOUT + g * Dd + sub * 16];
#pragma unroll
        for (int c4 = 0; c4 < 4; c4++) q4[c4] = *(const float4*)(qp + 4 * c4);
    }

    float e[KW];
#pragma unroll
    for (int j = 0; j < KW; j++) {
        const float* kr = &ks[(sidx + j) * KSTR + sub * 16];
        const float* rr = &rt[j * Dd + sub * 16];
        float a0 = 0.f, a1 = 0.f;
#pragma unroll
        for (int c4 = 0; c4 < 4; c4++) {
            float4 kv = *(const float4*)(kr + 4 * c4);
            float4 rv = *(const float4*)(rr + 4 * c4);
            a0 = fmaf(q4[c4].x, kv.x + rv.x, a0);
            a1 = fmaf(q4[c4].y, kv.y + rv.y, a1);
            a0 = fmaf(q4[c4].z, kv.z + rv.z, a0);
            a1 = fmaf(q4[c4].w, kv.w + rv.w, a1);
        }
        float acc = a0 + a1;
        acc += __shfl_xor_sync(0xffffffffu, acc, 8);
        acc += __shfl_xor_sync(0xffffffffu, acc, 16);
        e[j] = acc;
    }

    float mx = e[0];
#pragma unroll
    for (int j = 1; j < KW; j++) mx = fmaxf(mx, e[j]);
    float sum = 0.f;
#pragma unroll
    for (int j = 0; j < KW; j++) { e[j] = __expf(e[j] - mx); sum += e[j]; }
    const float inv = 1.f / sum;
#pragma unroll
    for (int j = 0; j < KW; j++) e[j] *= inv;

    {
        float* ap = &attn_out[((size_t)m * Gg + g) * KW];
#pragma unroll
        for (int u = 0; u < 4; u++) {
            const int j = sub * 4 + u;
            float val = (j == 0) ? e[0] : (j == 1) ? e[1] : (j == 2) ? e[2] :
                        (j == 3) ? e[3] : (j == 4) ? e[4] : (j == 5) ? e[5] :
                        (j == 6) ? e[6] : (j == 7) ? e[7] : (j == 8) ? e[8] :
                        (j == 9) ? e[9] : (j == 10) ? e[10] : (j == 11) ? e[11] :
                        (j == 12) ? e[12] : (j == 13) ? e[13] : (j == 14) ? e[14] : e[15];
            ap[j] = val;
        }
        if (sub == 0) ap[16] = e[16];
    }

    float4 o[4];
#pragma unroll
    for (int c4 = 0; c4 < 4; c4++) o[c4] = make_float4(0.f, 0.f, 0.f, 0.f);
#pragma unroll
    for (int j = 0; j < KW; j++) {
        const float* vr = &vs[(sidx + j) * KSTR + sub * 16];
        const float w = e[j];
#pragma unroll
        for (int c4 = 0; c4 < 4; c4++) {
            float4 vv = *(const float4*)(vr + 4 * c4);
            o[c4].x = fmaf(w, vv.x, o[c4].x);
            o[c4].y = fmaf(w, vv.y, o[c4].y);
            o[c4].z = fmaf(w, vv.z, o[c4].z);
            o[c4].w = fmaf(w, vv.w, o[c4].w);
        }
    }
    {
        float* op = &out[(size_t)m * FOUT + g * Dd + sub * 16];
#pragma unroll
        for (int c4 = 0; c4 < 4; c4++) *(float4*)(op + 4 * c4) = o[c4];
    }
}

// ---------------------------------------------------------------------------
extern "C" void kernel_launch(void* const* d_in, const int* in_sizes, int n_in,
                              void* d_out, int out_size)
{
    const float* x   = (const float*)d_in[0];
    const float* Wq  = (const float*)d_in[1];
    const float* Wk  = (const float*)d_in[2];
    const float* Wv  = (const float*)d_in[3];
    const float* rel = (const float*)d_in[4];

    float* out  = (float*)d_out;
    float* attn = out + (size_t)Mrows * FOUT;

    split_x<<<(Mrows * FIN / 4) / 256, 256>>>(x);
    split_w<<<dim3((FOUT * FIN / 4) / 256, 1, 3), 256>>>(Wq, Wk, Wv);

    dim3 gg(FOUT / 128, Mrows / 128, 3);
    gemm_all<<<gg, 256>>>();

    dim3 ga(Ss / TSs, Gg, Bb);
    attn2<<<ga, 256>>>(rel, out, attn);
}

// round 12
// speedup vs baseline: 1.0727x; 1.0067x over previous
#include <cuda_runtime.h>
#include <cuda_fp16.h>
#include <cstdint>

#define Bb   4
#define Ss   4096
#define FIN  512
#define FOUT 512
#define KW   17
#define Gg   8
#define Dd   64
#define PADK 8
#define Mrows (Bb*Ss)   // 16384

__device__ float g_q[(size_t)Mrows*FOUT];
__device__ float g_k[(size_t)Mrows*FOUT];
__device__ float g_v[(size_t)Mrows*FOUT];

// fp16 hi/lo split operands
__device__ __half g_xh[(size_t)Mrows*FIN];
__device__ __half g_xl[(size_t)Mrows*FIN];
__device__ __half g_wh[3][(size_t)FOUT*FIN];
__device__ __half g_wl[3][(size_t)FOUT*FIN];

// ---------------------------------------------------------------------------
__device__ __forceinline__ void mma_f16(float* d, const uint32_t* a,
                                        uint32_t b0, uint32_t b1) {
    asm volatile(
        "mma.sync.aligned.m16n8k16.row.col.f32.f16.f16.f32 "
        "{%0,%1,%2,%3}, {%4,%5,%6,%7}, {%8,%9}, {%0,%1,%2,%3};"
        : "+f"(d[0]), "+f"(d[1]), "+f"(d[2]), "+f"(d[3])
        : "r"(a[0]), "r"(a[1]), "r"(a[2]), "r"(a[3]), "r"(b0), "r"(b1));
}

__device__ __forceinline__ void cp_async16(void* smem, const void* gmem) {
    uint32_t s = (uint32_t)__cvta_generic_to_shared(smem);
    asm volatile("cp.async.cg.shared.global [%0], [%1], 16;" :: "r"(s), "l"(gmem));
}
__device__ __forceinline__ void cp_commit() { asm volatile("cp.async.commit_group;"); }
__device__ __forceinline__ void cp_wait0() { asm volatile("cp.async.wait_group 0;"); }

__device__ __forceinline__ uint64_t pack4h(__half a, __half b, __half c, __half d) {
    return (uint64_t)__half_as_ushort(a)
         | ((uint64_t)__half_as_ushort(b) << 16)
         | ((uint64_t)__half_as_ushort(c) << 32)
         | ((uint64_t)__half_as_ushort(d) << 48);
}

// ---------------------------------------------------------------------------
// Pre-pass: split fp32 -> fp16 hi + fp16 lo (residual).
// ---------------------------------------------------------------------------
__global__ __launch_bounds__(256) void split_x(const float* __restrict__ src) {
    const size_t i = (size_t)blockIdx.x * 256 + threadIdx.x;
    float4 v = ((const float4*)src)[i];
    float a[4] = {v.x, v.y, v.z, v.w};
    __half h[4], l[4];
#pragma unroll
    for (int u = 0; u < 4; u++) {
        h[u] = __float2half_rn(a[u]);
        l[u] = __float2half_rn(a[u] - __half2float(h[u]));
    }
    ((uint64_t*)g_xh)[i] = pack4h(h[0], h[1], h[2], h[3]);
    ((uint64_t*)g_xl)[i] = pack4h(l[0], l[1], l[2], l[3]);
}

__global__ __launch_bounds__(256) void split_w(const float* __restrict__ Wq,
                                               const float* __restrict__ Wk,
                                               const float* __restrict__ Wv) {
    const int z = blockIdx.z;
    const float* src = (z == 0) ? Wq : (z == 1) ? Wk : Wv;
    const size_t i = (size_t)blockIdx.x * 256 + threadIdx.x;
    float4 v = ((const float4*)src)[i];
    float a[4] = {v.x, v.y, v.z, v.w};
    __half h[4], l[4];
#pragma unroll
    for (int u = 0; u < 4; u++) {
        h[u] = __float2half_rn(a[u]);
        l[u] = __float2half_rn(a[u] - __half2float(h[u]));
    }
    ((uint64_t*)g_wh[z])[i] = pack4h(h[0], h[1], h[2], h[3]);
    ((uint64_t*)g_wl[z])[i] = pack4h(l[0], l[1], l[2], l[3]);
}

// ---------------------------------------------------------------------------
// Unified fp16 GEMM. z=0 (q): 3 passes (xh*Wh + xl*Wh + xh*Wl, residual 2^-22).
// z=1 (k), z=2 (v): 2 passes ((xh+xl)*Wh, error = one-sided W rounding 2^-11).
// 128x128 tile, BK=16, 256 thr, warp tile 32x64, k-slot remap, 2 CTAs/SM.
// ---------------------------------------------------------------------------
__global__ __launch_bounds__(256, 2) void gemm_all(void) {
    __shared__ __half Ah[2][2048];
    __shared__ __half Al[2][2048];
    __shared__ __half Bh[2][2048];
    __shared__ __half Bl[2][2048];

    const int z    = blockIdx.z;
    const bool threePass = (z == 0);
    const __half* __restrict__ Wh = g_wh[z];
    const __half* __restrict__ Wl = g_wl[z];
    float* __restrict__ C = (z == 0) ? g_q : (z == 1) ? g_k : g_v;

    const int tid  = threadIdx.x;
    const int m0   = blockIdx.y * 128;
    const int n0   = blockIdx.x * 128;

    const int lrow = tid >> 1;
    const int lk   = (tid & 1) * 8;    // 8 fp16 = 16 B

    const __half* agh = g_xh + (size_t)(m0 + lrow) * FIN + lk;
    const __half* agl = g_xl + (size_t)(m0 + lrow) * FIN + lk;
    const __half* bgh = Wh   + (size_t)(n0 + lrow) * FIN + lk;
    const __half* bgl = Wl   + (size_t)(n0 + lrow) * FIN + lk;
    __half* sah = &Ah[0][lrow * 16 + lk];
    __half* sal = &Al[0][lrow * 16 + lk];
    __half* sbh = &Bh[0][lrow * 16 + lk];
    __half* sbl = &Bl[0][lrow * 16 + lk];

    const int warp = tid >> 5;
    const int lane = tid & 31;
    const int wm0  = (warp >> 1) * 32;
    const int wn0  = (warp & 1) * 64;
    const int gid  = lane >> 2;
    const int tig  = lane & 3;

    float acc[2][8][4];
#pragma unroll
    for (int mt = 0; mt < 2; mt++)
#pragma unroll
        for (int nt = 0; nt < 8; nt++)
#pragma unroll
            for (int i = 0; i < 4; i++) acc[mt][nt][i] = 0.f;

    const int NT = FIN / 16;

    cp_async16(sah, agh);
    cp_async16(sal, agl);
    cp_async16(sbh, bgh);
    if (threePass) cp_async16(sbl, bgl);
    cp_commit();

    for (int t = 0; t < NT; t++) {
        cp_wait0();
        __syncthreads();

        if (t + 1 < NT) {
            const int nb = (t + 1) & 1;
            const int ko = (t + 1) * 16;
            cp_async16(sah + nb * 2048, agh + ko);
            cp_async16(sal + nb * 2048, agl + ko);
            cp_async16(sbh + nb * 2048, bgh + ko);
            if (threePass) cp_async16(sbl + nb * 2048, bgl + ko);
            cp_commit();
        }

        const __half* Abh = Ah[t & 1];
        const __half* Abl = Al[t & 1];
        const __half* Bbh = Bh[t & 1];
        const __half* Bbl = Bl[t & 1];

        uint32_t a_h[2][4], a_l[2][4];
#pragma unroll
        for (int mt = 0; mt < 2; mt++) {
            const int r0 = wm0 + mt * 16 + gid;
            uint2 v0 = *(const uint2*)&Abh[(r0    ) * 16 + 4 * tig];
            uint2 v1 = *(const uint2*)&Abh[(r0 + 8) * 16 + 4 * tig];
            a_h[mt][0] = v0.x; a_h[mt][1] = v1.x; a_h[mt][2] = v0.y; a_h[mt][3] = v1.y;
            uint2 w0 = *(const uint2*)&Abl[(r0    ) * 16 + 4 * tig];
            uint2 w1 = *(const uint2*)&Abl[(r0 + 8) * 16 + 4 * tig];
            a_l[mt][0] = w0.x; a_l[mt][1] = w1.x; a_l[mt][2] = w0.y; a_l[mt][3] = w1.y;
        }

#pragma unroll
        for (int nt = 0; nt < 8; nt++) {
            const int n = wn0 + nt * 8 + gid;
            uint2 vbh = *(const uint2*)&Bbh[n * 16 + 4 * tig];
#pragma unroll
            for (int mt = 0; mt < 2; mt++) {
                mma_f16(acc[mt][nt], a_h[mt], vbh.x, vbh.y);  // xh*Wh
                mma_f16(acc[mt][nt], a_l[mt], vbh.x, vbh.y);  // xl*Wh
            }
            if (threePass) {
                uint2 vbl = *(const uint2*)&Bbl[n * 16 + 4 * tig];
#pragma unroll
                for (int mt = 0; mt < 2; mt++)
                    mma_f16(acc[mt][nt], a_h[mt], vbl.x, vbl.y);  // xh*Wl
            }
        }
        __syncthreads();
    }

#pragma unroll
    for (int mt = 0; mt < 2; mt++) {
#pragma unroll
        for (int nt = 0; nt < 8; nt++) {
            const int row = m0 + wm0 + mt * 16 + gid;
            const int col = n0 + wn0 + nt * 8 + 2 * tig;
            *(float2*)&C[(size_t)row * FOUT + col] =
                make_float2(acc[mt][nt][0], acc[mt][nt][1]);
            *(float2*)&C[(size_t)(row + 8) * FOUT + col] =
                make_float2(acc[mt][nt][2], acc[mt][nt][3]);
        }
    }
}

// ---------------------------------------------------------------------------
// attn (unchanged from R11): block = (b, g, 64 s), occ hint 4 CTAs/SM.
// ---------------------------------------------------------------------------
#define TSs   64
#define RROWS 80          // TSs + KW - 1
#define KSTR  68

__global__ __launch_bounds__(256, 4) void attn2(
    const float* __restrict__ rel,     // [FOUT, KW]
    float* __restrict__ out,           // [Mrows, FOUT]
    float* __restrict__ attn_out)      // [Mrows, Gg, KW]
{
    __shared__ float ks[RROWS * KSTR];
    __shared__ float vs[RROWS * KSTR];
    __shared__ float rt[KW * Dd];      // relT[j][d]

    const int b   = blockIdx.z;
    const int g   = blockIdx.y;
    const int s0  = blockIdx.x * TSs;
    const int tid = threadIdx.x;
    const int lane = tid & 31, warp = tid >> 5;
    const int sub  = lane >> 3;               // 0..3
    const int sidx = warp * 8 + (lane & 7);   // 0..63
    const int s    = s0 + sidx;
    const int m    = b * Ss + s;

    for (int i = tid; i < RROWS * 16; i += 256) {
        const int r = i >> 4, c = (i & 15) * 4;
        const int gr = s0 - PADK + r;
        float* kd = &ks[r * KSTR + c];
        float* vd = &vs[r * KSTR + c];
        if (gr >= 0 && gr < Ss) {
            const size_t gbase = ((size_t)(b * Ss + gr)) * FOUT + g * Dd + c;
            cp_async16(kd, &g_k[gbase]);
            cp_async16(vd, &g_v[gbase]);
        } else {
            *(float4*)kd = make_float4(0.f, 0.f, 0.f, 0.f);
            *(float4*)vd = make_float4(0.f, 0.f, 0.f, 0.f);
        }
    }
    {
        const float* rsrc = rel + (size_t)g * Dd * KW;
        for (int i = tid; i < (Dd * KW) / 4; i += 256) {
            float4 v4 = *(const float4*)(rsrc + i * 4);
            float vv[4] = {v4.x, v4.y, v4.z, v4.w};
#pragma unroll
            for (int u = 0; u < 4; u++) {
                const int f = i * 4 + u;
                const int d = f / KW, j = f % KW;
                rt[j * Dd + d] = vv[u];
            }
        }
    }
    cp_commit();
    cp_wait0();
    __syncthreads();

    float4 q4[4];
    {
        const float* qp = &g_q[(size_t)m * FOUT + g * Dd + sub * 16];
#pragma unroll
        for (int c4 = 0; c4 < 4; c4++) q4[c4] = *(const float4*)(qp + 4 * c4);
    }

    float e[KW];
#pragma unroll
    for (int j = 0; j < KW; j++) {
        const float* kr = &ks[(sidx + j) * KSTR + sub * 16];
        const float* rr = &rt[j * Dd + sub * 16];
        float a0 = 0.f, a1 = 0.f;
#pragma unroll
        for (int c4 = 0; c4 < 4; c4++) {
            float4 kv = *(const float4*)(kr + 4 * c4);
            float4 rv = *(const float4*)(rr + 4 * c4);
            a0 = fmaf(q4[c4].x, kv.x + rv.x, a0);
            a1 = fmaf(q4[c4].y, kv.y + rv.y, a1);
            a0 = fmaf(q4[c4].z, kv.z + rv.z, a0);
            a1 = fmaf(q4[c4].w, kv.w + rv.w, a1);
        }
        float acc = a0 + a1;
        acc += __shfl_xor_sync(0xffffffffu, acc, 8);
        acc += __shfl_xor_sync(0xffffffffu, acc, 16);
        e[j] = acc;
    }

    float mx = e[0];
#pragma unroll
    for (int j = 1; j < KW; j++) mx = fmaxf(mx, e[j]);
    float sum = 0.f;
#pragma unroll
    for (int j = 0; j < KW; j++) { e[j] = __expf(e[j] - mx); sum += e[j]; }
    const float inv = 1.f / sum;
#pragma unroll
    for (int j = 0; j < KW; j++) e[j] *= inv;

    {
        float* ap = &attn_out[((size_t)m * Gg + g) * KW];
#pragma unroll
        for (int u = 0; u < 4; u++) {
            const int j = sub * 4 + u;
            float val = (j == 0) ? e[0] : (j == 1) ? e[1] : (j == 2) ? e[2] :
                        (j == 3) ? e[3] : (j == 4) ? e[4] : (j == 5) ? e[5] :
                        (j == 6) ? e[6] : (j == 7) ? e[7] : (j == 8) ? e[8] :
                        (j == 9) ? e[9] : (j == 10) ? e[10] : (j == 11) ? e[11] :
                        (j == 12) ? e[12] : (j == 13) ? e[13] : (j == 14) ? e[14] : e[15];
            ap[j] = val;
        }
        if (sub == 0) ap[16] = e[16];
    }

    float4 o[4];
#pragma unroll
    for (int c4 = 0; c4 < 4; c4++) o[c4] = make_float4(0.f, 0.f, 0.f, 0.f);
#pragma unroll
    for (int j = 0; j < KW; j++) {
        const float* vr = &vs[(sidx + j) * KSTR + sub * 16];
        const float w = e[j];
#pragma unroll
        for (int c4 = 0; c4 < 4; c4++) {
            float4 vv = *(const float4*)(vr + 4 * c4);
            o[c4].x = fmaf(w, vv.x, o[c4].x);
            o[c4].y = fmaf(w, vv.y, o[c4].y);
            o[c4].z = fmaf(w, vv.z, o[c4].z);
            o[c4].w = fmaf(w, vv.w, o[c4].w);
        }
    }
    {
        float* op = &out[(size_t)m * FOUT + g * Dd + sub * 16];
#pragma unroll
        for (int c4 = 0; c4 < 4; c4++) *(float4*)(op + 4 * c4) = o[c4];
    }
}

// ---------------------------------------------------------------------------
extern "C" void kernel_launch(void* const* d_in, const int* in_sizes, int n_in,
                              void* d_out, int out_size)
{
    const float* x   = (const float*)d_in[0];
    const float* Wq  = (const float*)d_in[1];
    const float* Wk  = (const float*)d_in[2];
    const float* Wv  = (const float*)d_in[3];
    const float* rel = (const float*)d_in[4];

    float* out  = (float*)d_out;
    float* attn = out + (size_t)Mrows * FOUT;

    split_x<<<(Mrows * FIN / 4) / 256, 256>>>(x);
    split_w<<<dim3((FOUT * FIN / 4) / 256, 1, 3), 256>>>(Wq, Wk, Wv);

    dim3 gg(FOUT / 128, Mrows / 128, 3);
    gemm_all<<<gg, 256>>>();

    dim3 ga(Ss / TSs, Gg, Bb);
    attn2<<<ga, 256>>>(rel, out, attn);
}

// round 13
// speedup vs baseline: 1.0855x; 1.0119x over previous
#include <cuda_runtime.h>
#include <cuda_fp16.h>
#include <cstdint>

#define Bb   4
#define Ss   4096
#define FIN  512
#define FOUT 512
#define KW   17
#define Gg   8
#define Dd   64
#define PADK 8
#define Mrows (Bb*Ss)   // 16384

__device__ float g_q[(size_t)Mrows*FOUT];
__device__ float g_k[(size_t)Mrows*FOUT];
__device__ __half g_vh[(size_t)Mrows*FOUT];   // v output, fp16 (attn is sole consumer)

// fp16 hi/lo split operands
__device__ __half g_xh[(size_t)Mrows*FIN];
__device__ __half g_xl[(size_t)Mrows*FIN];
__device__ __half g_wh[3][(size_t)FOUT*FIN];
__device__ __half g_wl[3][(size_t)FOUT*FIN];

__device__ unsigned int g_ctr;   // persistent-GEMM tile counter

// ---------------------------------------------------------------------------
__device__ __forceinline__ void mma_f16(float* d, const uint32_t* a,
                                        uint32_t b0, uint32_t b1) {
    asm volatile(
        "mma.sync.aligned.m16n8k16.row.col.f32.f16.f16.f32 "
        "{%0,%1,%2,%3}, {%4,%5,%6,%7}, {%8,%9}, {%0,%1,%2,%3};"
        : "+f"(d[0]), "+f"(d[1]), "+f"(d[2]), "+f"(d[3])
        : "r"(a[0]), "r"(a[1]), "r"(a[2]), "r"(a[3]), "r"(b0), "r"(b1));
}

__device__ __forceinline__ void cp_async16(void* smem, const void* gmem) {
    uint32_t s = (uint32_t)__cvta_generic_to_shared(smem);
    asm volatile("cp.async.cg.shared.global [%0], [%1], 16;" :: "r"(s), "l"(gmem));
}
__device__ __forceinline__ void cp_commit() { asm volatile("cp.async.commit_group;"); }
__device__ __forceinline__ void cp_wait0() { asm volatile("cp.async.wait_group 0;"); }

__device__ __forceinline__ uint64_t pack4h(__half a, __half b, __half c, __half d) {
    return (uint64_t)__half_as_ushort(a)
         | ((uint64_t)__half_as_ushort(b) << 16)
         | ((uint64_t)__half_as_ushort(c) << 32)
         | ((uint64_t)__half_as_ushort(d) << 48);
}

// ---------------------------------------------------------------------------
// Pre-pass: split fp32 -> fp16 hi + fp16 lo. split_x also resets tile counter.
// ---------------------------------------------------------------------------
__global__ __launch_bounds__(256) void split_x(const float* __restrict__ src) {
    if (blockIdx.x == 0 && threadIdx.x == 0) g_ctr = 0u;
    const size_t i = (size_t)blockIdx.x * 256 + threadIdx.x;
    float4 v = ((const float4*)src)[i];
    float a[4] = {v.x, v.y, v.z, v.w};
    __half h[4], l[4];
#pragma unroll
    for (int u = 0; u < 4; u++) {
        h[u] = __float2half_rn(a[u]);
        l[u] = __float2half_rn(a[u] - __half2float(h[u]));
    }
    ((uint64_t*)g_xh)[i] = pack4h(h[0], h[1], h[2], h[3]);
    ((uint64_t*)g_xl)[i] = pack4h(l[0], l[1], l[2], l[3]);
}

__global__ __launch_bounds__(256) void split_w(const float* __restrict__ Wq,
                                               const float* __restrict__ Wk,
                                               const float* __restrict__ Wv) {
    const int z = blockIdx.z;
    const float* src = (z == 0) ? Wq : (z == 1) ? Wk : Wv;
    const size_t i = (size_t)blockIdx.x * 256 + threadIdx.x;
    float4 v = ((const float4*)src)[i];
    float a[4] = {v.x, v.y, v.z, v.w};
    __half h[4], l[4];
#pragma unroll
    for (int u = 0; u < 4; u++) {
        h[u] = __float2half_rn(a[u]);
        l[u] = __float2half_rn(a[u] - __half2float(h[u]));
    }
    ((uint64_t*)g_wh[z])[i] = pack4h(h[0], h[1], h[2], h[3]);
    ((uint64_t*)g_wl[z])[i] = pack4h(l[0], l[1], l[2], l[3]);
}

// ---------------------------------------------------------------------------
// Persistent fp16 GEMM: 296 CTAs dynamically pull 1536 tiles (3-pass q tiles
// first = LPT). z=0 q: 3 passes; z=1 k: 2 passes; z=2 v: 2 passes + fp16 out.
// ---------------------------------------------------------------------------
#define NTILES 1536   // 3 * 128 * 4

__global__ __launch_bounds__(256, 2) void gemm_all(void) {
    __shared__ __half Ah[2][2048];
    __shared__ __half Al[2][2048];
    __shared__ __half Bh[2][2048];
    __shared__ __half Bl[2][2048];
    __shared__ int s_tile;

    const int tid  = threadIdx.x;
    const int lrow = tid >> 1;
    const int lk   = (tid & 1) * 8;

    const int warp = tid >> 5;
    const int lane = tid & 31;
    const int wm0  = (warp >> 1) * 32;
    const int wn0  = (warp & 1) * 64;
    const int gid  = lane >> 2;
    const int tig  = lane & 3;

    __half* sah = &Ah[0][lrow * 16 + lk];
    __half* sal = &Al[0][lrow * 16 + lk];
    __half* sbh = &Bh[0][lrow * 16 + lk];
    __half* sbl = &Bl[0][lrow * 16 + lk];

    const int NT = FIN / 16;

    while (true) {
        if (tid == 0) s_tile = (int)atomicAdd(&g_ctr, 1u);
        __syncthreads();   // publish s_tile; also fences smem reuse across tiles
        const int t0 = s_tile;
        if (t0 >= NTILES) break;

        const int z   = t0 >> 9;          // 512 tiles per z; z=0 (3-pass) first
        const int rem = t0 & 511;
        const int m0  = (rem >> 2) * 128;
        const int n0  = (rem & 3) * 128;
        const bool threePass = (z == 0);

        const __half* __restrict__ Wh = g_wh[z];
        const __half* __restrict__ Wl = g_wl[z];

        const __half* agh = g_xh + (size_t)(m0 + lrow) * FIN + lk;
        const __half* agl = g_xl + (size_t)(m0 + lrow) * FIN + lk;
        const __half* bgh = Wh   + (size_t)(n0 + lrow) * FIN + lk;
        const __half* bgl = Wl   + (size_t)(n0 + lrow) * FIN + lk;

        float acc[2][8][4];
#pragma unroll
        for (int mt = 0; mt < 2; mt++)
#pragma unroll
            for (int nt = 0; nt < 8; nt++)
#pragma unroll
                for (int i = 0; i < 4; i++) acc[mt][nt][i] = 0.f;

        cp_async16(sah, agh);
        cp_async16(sal, agl);
        cp_async16(sbh, bgh);
        if (threePass) cp_async16(sbl, bgl);
        cp_commit();

        for (int t = 0; t < NT; t++) {
            cp_wait0();
            __syncthreads();

            if (t + 1 < NT) {
                const int nb = (t + 1) & 1;
                const int ko = (t + 1) * 16;
                cp_async16(sah + nb * 2048, agh + ko);
                cp_async16(sal + nb * 2048, agl + ko);
                cp_async16(sbh + nb * 2048, bgh + ko);
                if (threePass) cp_async16(sbl + nb * 2048, bgl + ko);
                cp_commit();
            }

            const __half* Abh = Ah[t & 1];
            const __half* Abl = Al[t & 1];
            const __half* Bbh = Bh[t & 1];
            const __half* Bbl = Bl[t & 1];

            uint32_t a_h[2][4], a_l[2][4];
#pragma unroll
            for (int mt = 0; mt < 2; mt++) {
                const int r0 = wm0 + mt * 16 + gid;
                uint2 v0 = *(const uint2*)&Abh[(r0    ) * 16 + 4 * tig];
                uint2 v1 = *(const uint2*)&Abh[(r0 + 8) * 16 + 4 * tig];
                a_h[mt][0] = v0.x; a_h[mt][1] = v1.x; a_h[mt][2] = v0.y; a_h[mt][3] = v1.y;
                uint2 w0 = *(const uint2*)&Abl[(r0    ) * 16 + 4 * tig];
                uint2 w1 = *(const uint2*)&Abl[(r0 + 8) * 16 + 4 * tig];
                a_l[mt][0] = w0.x; a_l[mt][1] = w1.x; a_l[mt][2] = w0.y; a_l[mt][3] = w1.y;
            }

#pragma unroll
            for (int nt = 0; nt < 8; nt++) {
                const int n = wn0 + nt * 8 + gid;
                uint2 vbh = *(const uint2*)&Bbh[n * 16 + 4 * tig];
#pragma unroll
                for (int mt = 0; mt < 2; mt++) {
                    mma_f16(acc[mt][nt], a_h[mt], vbh.x, vbh.y);  // xh*Wh
                    mma_f16(acc[mt][nt], a_l[mt], vbh.x, vbh.y);  // xl*Wh
                }
                if (threePass) {
                    uint2 vbl = *(const uint2*)&Bbl[n * 16 + 4 * tig];
#pragma unroll
                    for (int mt = 0; mt < 2; mt++)
                        mma_f16(acc[mt][nt], a_h[mt], vbl.x, vbl.y);  // xh*Wl
                }
            }
            __syncthreads();
        }

        if (z < 2) {
            float* __restrict__ C = (z == 0) ? g_q : g_k;
#pragma unroll
            for (int mt = 0; mt < 2; mt++) {
#pragma unroll
                for (int nt = 0; nt < 8; nt++) {
                    const int row = m0 + wm0 + mt * 16 + gid;
                    const int col = n0 + wn0 + nt * 8 + 2 * tig;
                    *(float2*)&C[(size_t)row * FOUT + col] =
                        make_float2(acc[mt][nt][0], acc[mt][nt][1]);
                    *(float2*)&C[(size_t)(row + 8) * FOUT + col] =
                        make_float2(acc[mt][nt][2], acc[mt][nt][3]);
                }
            }
        } else {
#pragma unroll
            for (int mt = 0; mt < 2; mt++) {
#pragma unroll
                for (int nt = 0; nt < 8; nt++) {
                    const int row = m0 + wm0 + mt * 16 + gid;
                    const int col = n0 + wn0 + nt * 8 + 2 * tig;
                    *(__half2*)&g_vh[(size_t)row * FOUT + col] =
                        __floats2half2_rn(acc[mt][nt][0], acc[mt][nt][1]);
                    *(__half2*)&g_vh[(size_t)(row + 8) * FOUT + col] =
                        __floats2half2_rn(acc[mt][nt][2], acc[mt][nt][3]);
                }
            }
        }
    }
}

// ---------------------------------------------------------------------------
// attn: k fp32 (stride 68), v fp16 (stride 72 halves -> 144B row spacing,
// conflict-free). v converted half2->float2 in registers.
// ---------------------------------------------------------------------------
#define TSs   64
#define RROWS 80          // TSs + KW - 1
#define KSTR  68
#define VSTR  72

__global__ __launch_bounds__(256, 4) void attn2(
    const float* __restrict__ rel,     // [FOUT, KW]
    float* __restrict__ out,           // [Mrows, FOUT]
    float* __restrict__ attn_out)      // [Mrows, Gg, KW]
{
    __shared__ float  ks[RROWS * KSTR];
    __shared__ __half vs[RROWS * VSTR];
    __shared__ float  rt[KW * Dd];     // relT[j][d]

    const int b   = blockIdx.z;
    const int g   = blockIdx.y;
    const int s0  = blockIdx.x * TSs;
    const int tid = threadIdx.x;
    const int lane = tid & 31, warp = tid >> 5;
    const int sub  = lane >> 3;               // 0..3
    const int sidx = warp * 8 + (lane & 7);   // 0..63
    const int s    = s0 + sidx;
    const int m    = b * Ss + s;

    // k tile: fp32, 16 float4 chunks per row
    for (int i = tid; i < RROWS * 16; i += 256) {
        const int r = i >> 4, c = (i & 15) * 4;
        const int gr = s0 - PADK + r;
        float* kd = &ks[r * KSTR + c];
        if (gr >= 0 && gr < Ss) {
            cp_async16(kd, &g_k[((size_t)(b * Ss + gr)) * FOUT + g * Dd + c]);
        } else {
            *(float4*)kd = make_float4(0.f, 0.f, 0.f, 0.f);
        }
    }
    // v tile: fp16, 8 x 16B chunks per row (8 halves each)
    for (int i = tid; i < RROWS * 8; i += 256) {
        const int r = i >> 3, c = (i & 7) * 8;   // c in halves
        const int gr = s0 - PADK + r;
        __half* vd = &vs[r * VSTR + c];
        if (gr >= 0 && gr < Ss) {
            cp_async16(vd, &g_vh[((size_t)(b * Ss + gr)) * FOUT + g * Dd + c]);
        } else {
            *(uint4*)vd = make_uint4(0u, 0u, 0u, 0u);
        }
    }
    // relT: coalesced read of contiguous g-slice, scatter to [j][d]
    {
        const float* rsrc = rel + (size_t)g * Dd * KW;
        for (int i = tid; i < (Dd * KW) / 4; i += 256) {
            float4 v4 = *(const float4*)(rsrc + i * 4);
            float vv[4] = {v4.x, v4.y, v4.z, v4.w};
#pragma unroll
            for (int u = 0; u < 4; u++) {
                const int f = i * 4 + u;
                const int d = f / KW, j = f % KW;
                rt[j * Dd + d] = vv[u];
            }
        }
    }
    cp_commit();
    cp_wait0();
    __syncthreads();

    float4 q4[4];
    {
        const float* qp = &g_q[(size_t)m * FOUT + g * Dd + sub * 16];
#pragma unroll
        for (int c4 = 0; c4 < 4; c4++) q4[c4] = *(const float4*)(qp + 4 * c4);
    }

    float e[KW];
#pragma unroll
    for (int j = 0; j < KW; j++) {
        const float* kr = &ks[(sidx + j) * KSTR + sub * 16];
        const float* rr = &rt[j * Dd + sub * 16];
        float a0 = 0.f, a1 = 0.f;
#pragma unroll
        for (int c4 = 0; c4 < 4; c4++) {
            float4 kv = *(const float4*)(kr + 4 * c4);
            float4 rv = *(const float4*)(rr + 4 * c4);
            a0 = fmaf(q4[c4].x, kv.x + rv.x, a0);
            a1 = fmaf(q4[c4].y, kv.y + rv.y, a1);
            a0 = fmaf(q4[c4].z, kv.z + rv.z, a0);
            a1 = fmaf(q4[c4].w, kv.w + rv.w, a1);
        }
        float acc = a0 + a1;
        acc += __shfl_xor_sync(0xffffffffu, acc, 8);
        acc += __shfl_xor_sync(0xffffffffu, acc, 16);
        e[j] = acc;
    }

    float mx = e[0];
#pragma unroll
    for (int j = 1; j < KW; j++) mx = fmaxf(mx, e[j]);
    float sum = 0.f;
#pragma unroll
    for (int j = 0; j < KW; j++) { e[j] = __expf(e[j] - mx); sum += e[j]; }
    const float inv = 1.f / sum;
#pragma unroll
    for (int j = 0; j < KW; j++) e[j] *= inv;

    {
        float* ap = &attn_out[((size_t)m * Gg + g) * KW];
#pragma unroll
        for (int u = 0; u < 4; u++) {
            const int j = sub * 4 + u;
            float val = (j == 0) ? e[0] : (j == 1) ? e[1] : (j == 2) ? e[2] :
                        (j == 3) ? e[3] : (j == 4) ? e[4] : (j == 5) ? e[5] :
                        (j == 6) ? e[6] : (j == 7) ? e[7] : (j == 8) ? e[8] :
                        (j == 9) ? e[9] : (j == 10) ? e[10] : (j == 11) ? e[11] :
                        (j == 12) ? e[12] : (j == 13) ? e[13] : (j == 14) ? e[14] : e[15];
            ap[j] = val;
        }
        if (sub == 0) ap[16] = e[16];
    }

    float o[16];
#pragma unroll
    for (int u = 0; u < 16; u++) o[u] = 0.f;
#pragma unroll
    for (int j = 0; j < KW; j++) {
        const __half* vr = &vs[(sidx + j) * VSTR + sub * 16];
        uint4 p0 = *(const uint4*)vr;        // halves 0..7
        uint4 p1 = *(const uint4*)(vr + 8);  // halves 8..15
        uint32_t pw[8] = {p0.x, p0.y, p0.z, p0.w, p1.x, p1.y, p1.z, p1.w};
        const float w = e[j];
#pragma unroll
        for (int u = 0; u < 8; u++) {
            float2 f = __half22float2(*(const __half2*)&pw[u]);
            o[2 * u]     = fmaf(w, f.x, o[2 * u]);
            o[2 * u + 1] = fmaf(w, f.y, o[2 * u + 1]);
        }
    }
    {
        float* op = &out[(size_t)m * FOUT + g * Dd + sub * 16];
#pragma unroll
        for (int c4 = 0; c4 < 4; c4++)
            *(float4*)(op + 4 * c4) =
                make_float4(o[4*c4], o[4*c4+1], o[4*c4+2], o[4*c4+3]);
    }
}

// ---------------------------------------------------------------------------
extern "C" void kernel_launch(void* const* d_in, const int* in_sizes, int n_in,
                              void* d_out, int out_size)
{
    const float* x   = (const float*)d_in[0];
    const float* Wq  = (const float*)d_in[1];
    const float* Wk  = (const float*)d_in[2];
    const float* Wv  = (const float*)d_in[3];
    const float* rel = (const float*)d_in[4];

    float* out  = (float*)d_out;
    float* attn = out + (size_t)Mrows * FOUT;

    split_x<<<(Mrows * FIN / 4) / 256, 256>>>(x);
    split_w<<<dim3((FOUT * FIN / 4) / 256, 1, 3), 256>>>(Wq, Wk, Wv);

    gemm_all<<<296, 256>>>();

    dim3 ga(Ss / TSs, Gg, Bb);
    attn2<<<ga, 256>>>(rel, out, attn);
}

// round 14
// speedup vs baseline: 1.0985x; 1.0120x over previous
#include <cuda_runtime.h>
#include <cuda_fp16.h>
#include <cstdint>

#define Bb   4
#define Ss   4096
#define FIN  512
#define FOUT 512
#define KW   17
#define Gg   8
#define Dd   64
#define PADK 8
#define Mrows (Bb*Ss)   // 16384

__device__ float g_q[(size_t)Mrows*FOUT];
__device__ float g_k[(size_t)Mrows*FOUT];
__device__ __half g_vh[(size_t)Mrows*FOUT];   // v output, fp16 (attn is sole consumer)

// fp16 hi/lo split operands
__device__ __half g_xh[(size_t)Mrows*FIN];
__device__ __half g_xl[(size_t)Mrows*FIN];
__device__ __half g_wh[3][(size_t)FOUT*FIN];
__device__ __half g_wl[3][(size_t)FOUT*FIN];

__device__ unsigned int g_ctr;   // persistent-GEMM tile counter

// ---------------------------------------------------------------------------
__device__ __forceinline__ void mma_f16(float* d, const uint32_t* a,
                                        uint32_t b0, uint32_t b1) {
    asm volatile(
        "mma.sync.aligned.m16n8k16.row.col.f32.f16.f16.f32 "
        "{%0,%1,%2,%3}, {%4,%5,%6,%7}, {%8,%9}, {%0,%1,%2,%3};"
        : "+f"(d[0]), "+f"(d[1]), "+f"(d[2]), "+f"(d[3])
        : "r"(a[0]), "r"(a[1]), "r"(a[2]), "r"(a[3]), "r"(b0), "r"(b1));
}

__device__ __forceinline__ void cp_async16(void* smem, const void* gmem) {
    uint32_t s = (uint32_t)__cvta_generic_to_shared(smem);
    asm volatile("cp.async.cg.shared.global [%0], [%1], 16;" :: "r"(s), "l"(gmem));
}
__device__ __forceinline__ void cp_commit() { asm volatile("cp.async.commit_group;"); }
__device__ __forceinline__ void cp_wait0() { asm volatile("cp.async.wait_group 0;"); }

__device__ __forceinline__ uint64_t pack4h(__half a, __half b, __half c, __half d) {
    return (uint64_t)__half_as_ushort(a)
         | ((uint64_t)__half_as_ushort(b) << 16)
         | ((uint64_t)__half_as_ushort(c) << 32)
         | ((uint64_t)__half_as_ushort(d) << 48);
}

// ---------------------------------------------------------------------------
// Fused pre-pass: one launch splits x AND Wq/Wk/Wv to fp16 hi/lo; resets ctr.
// Index space: [0, XN4) -> x; [XN4, XN4+3*WN4) -> weights (block-uniform z).
// ---------------------------------------------------------------------------
#define XN4 ((size_t)Mrows * FIN / 4)    // 2097152 float4s (div by 256)
#define WN4 ((size_t)FOUT * FIN / 4)     // 65536 float4s (div by 256)

__global__ __launch_bounds__(256) void split_all(const float* __restrict__ x,
                                                 const float* __restrict__ Wq,
                                                 const float* __restrict__ Wk,
                                                 const float* __restrict__ Wv) {
    const size_t i = (size_t)blockIdx.x * 256 + threadIdx.x;
    if (i == 0) g_ctr = 0u;

    const float* src;
    uint64_t *dh, *dl;
    size_t idx;
    if (i < XN4) {
        src = x; idx = i;
        dh = (uint64_t*)g_xh; dl = (uint64_t*)g_xl;
    } else {
        const size_t j = i - XN4;
        const int z = (int)(j / WN4);
        idx = j % WN4;
        src = (z == 0) ? Wq : (z == 1) ? Wk : Wv;
        dh = (uint64_t*)g_wh[z]; dl = (uint64_t*)g_wl[z];
    }
    float4 v = ((const float4*)src)[idx];
    float a[4] = {v.x, v.y, v.z, v.w};
    __half h[4], l[4];
#pragma unroll
    for (int u = 0; u < 4; u++) {
        h[u] = __float2half_rn(a[u]);
        l[u] = __float2half_rn(a[u] - __half2float(h[u]));
    }
    dh[idx] = pack4h(h[0], h[1], h[2], h[3]);
    dl[idx] = pack4h(l[0], l[1], l[2], l[3]);
}

// ---------------------------------------------------------------------------
// Persistent fp16 GEMM: 296 CTAs pull 1536 tiles (3-pass q tiles first = LPT).
// z=0 q: 3 passes; z=1 k: 2 passes; z=2 v: 2 passes + fp16 out.
// R14: single __syncthreads per k-tile (bottom barrier was redundant — the
// top barrier of iter t+1 already orders compute(t) before overwrite of buf t).
// ---------------------------------------------------------------------------
#define NTILES 1536   // 3 * 128 * 4

__global__ __launch_bounds__(256, 2) void gemm_all(void) {
    __shared__ __half Ah[2][2048];
    __shared__ __half Al[2][2048];
    __shared__ __half Bh[2][2048];
    __shared__ __half Bl[2][2048];
    __shared__ int s_tile;

    const int tid  = threadIdx.x;
    const int lrow = tid >> 1;
    const int lk   = (tid & 1) * 8;

    const int warp = tid >> 5;
    const int lane = tid & 31;
    const int wm0  = (warp >> 1) * 32;
    const int wn0  = (warp & 1) * 64;
    const int gid  = lane >> 2;
    const int tig  = lane & 3;

    __half* sah = &Ah[0][lrow * 16 + lk];
    __half* sal = &Al[0][lrow * 16 + lk];
    __half* sbh = &Bh[0][lrow * 16 + lk];
    __half* sbl = &Bl[0][lrow * 16 + lk];

    const int NT = FIN / 16;

    while (true) {
        if (tid == 0) s_tile = (int)atomicAdd(&g_ctr, 1u);
        __syncthreads();   // publish s_tile; also gates smem reuse across tiles
        const int t0 = s_tile;
        if (t0 >= NTILES) break;

        const int z   = t0 >> 9;          // 512 tiles per z; z=0 (3-pass) first
        const int rem = t0 & 511;
        const int m0  = (rem >> 2) * 128;
        const int n0  = (rem & 3) * 128;
        const bool threePass = (z == 0);

        const __half* __restrict__ Wh = g_wh[z];
        const __half* __restrict__ Wl = g_wl[z];

        const __half* agh = g_xh + (size_t)(m0 + lrow) * FIN + lk;
        const __half* agl = g_xl + (size_t)(m0 + lrow) * FIN + lk;
        const __half* bgh = Wh   + (size_t)(n0 + lrow) * FIN + lk;
        const __half* bgl = Wl   + (size_t)(n0 + lrow) * FIN + lk;

        float acc[2][8][4];
#pragma unroll
        for (int mt = 0; mt < 2; mt++)
#pragma unroll
            for (int nt = 0; nt < 8; nt++)
#pragma unroll
                for (int i = 0; i < 4; i++) acc[mt][nt][i] = 0.f;

        cp_async16(sah, agh);
        cp_async16(sal, agl);
        cp_async16(sbh, bgh);
        if (threePass) cp_async16(sbl, bgl);
        cp_commit();

        for (int t = 0; t < NT; t++) {
            cp_wait0();
            __syncthreads();   // data for chunk t visible; compute(t-1) done in all warps

            if (t + 1 < NT) {
                const int nb = (t + 1) & 1;
                const int ko = (t + 1) * 16;
                cp_async16(sah + nb * 2048, agh + ko);
                cp_async16(sal + nb * 2048, agl + ko);
                cp_async16(sbh + nb * 2048, bgh + ko);
                if (threePass) cp_async16(sbl + nb * 2048, bgl + ko);
                cp_commit();
            }

            const __half* Abh = Ah[t & 1];
            const __half* Abl = Al[t & 1];
            const __half* Bbh = Bh[t & 1];
            const __half* Bbl = Bl[t & 1];

            uint32_t a_h[2][4], a_l[2][4];
#pragma unroll
            for (int mt = 0; mt < 2; mt++) {
                const int r0 = wm0 + mt * 16 + gid;
                uint2 v0 = *(const uint2*)&Abh[(r0    ) * 16 + 4 * tig];
                uint2 v1 = *(const uint2*)&Abh[(r0 + 8) * 16 + 4 * tig];
                a_h[mt][0] = v0.x; a_h[mt][1] = v1.x; a_h[mt][2] = v0.y; a_h[mt][3] = v1.y;
                uint2 w0 = *(const uint2*)&Abl[(r0    ) * 16 + 4 * tig];
                uint2 w1 = *(const uint2*)&Abl[(r0 + 8) * 16 + 4 * tig];
                a_l[mt][0] = w0.x; a_l[mt][1] = w1.x; a_l[mt][2] = w0.y; a_l[mt][3] = w1.y;
            }

#pragma unroll
            for (int nt = 0; nt < 8; nt++) {
                const int n = wn0 + nt * 8 + gid;
                uint2 vbh = *(const uint2*)&Bbh[n * 16 + 4 * tig];
#pragma unroll
                for (int mt = 0; mt < 2; mt++) {
                    mma_f16(acc[mt][nt], a_h[mt], vbh.x, vbh.y);  // xh*Wh
                    mma_f16(acc[mt][nt], a_l[mt], vbh.x, vbh.y);  // xl*Wh
                }
                if (threePass) {
                    uint2 vbl = *(const uint2*)&Bbl[n * 16 + 4 * tig];
#pragma unroll
                    for (int mt = 0; mt < 2; mt++)
                        mma_f16(acc[mt][nt], a_h[mt], vbl.x, vbl.y);  // xh*Wl
                }
            }
            // (no bottom barrier — top barrier of next iteration provides ordering)
        }

        if (z < 2) {
            float* __restrict__ C = (z == 0) ? g_q : g_k;
#pragma unroll
            for (int mt = 0; mt < 2; mt++) {
#pragma unroll
                for (int nt = 0; nt < 8; nt++) {
                    const int row = m0 + wm0 + mt * 16 + gid;
                    const int col = n0 + wn0 + nt * 8 + 2 * tig;
                    *(float2*)&C[(size_t)row * FOUT + col] =
                        make_float2(acc[mt][nt][0], acc[mt][nt][1]);
                    *(float2*)&C[(size_t)(row + 8) * FOUT + col] =
                        make_float2(acc[mt][nt][2], acc[mt][nt][3]);
                }
            }
        } else {
#pragma unroll
            for (int mt = 0; mt < 2; mt++) {
#pragma unroll
                for (int nt = 0; nt < 8; nt++) {
                    const int row = m0 + wm0 + mt * 16 + gid;
                    const int col = n0 + wn0 + nt * 8 + 2 * tig;
                    *(__half2*)&g_vh[(size_t)row * FOUT + col] =
                        __floats2half2_rn(acc[mt][nt][0], acc[mt][nt][1]);
                    *(__half2*)&g_vh[(size_t)(row + 8) * FOUT + col] =
                        __floats2half2_rn(acc[mt][nt][2], acc[mt][nt][3]);
                }
            }
        }
    }
}

// ---------------------------------------------------------------------------
// attn (unchanged from R13): k fp32 (stride 68), v fp16 (stride 72 halves).
// ---------------------------------------------------------------------------
#define TSs   64
#define RROWS 80          // TSs + KW - 1
#define KSTR  68
#define VSTR  72

__global__ __launch_bounds__(256, 4) void attn2(
    const float* __restrict__ rel,     // [FOUT, KW]
    float* __restrict__ out,           // [Mrows, FOUT]
    float* __restrict__ attn_out)      // [Mrows, Gg, KW]
{
    __shared__ float  ks[RROWS * KSTR];
    __shared__ __half vs[RROWS * VSTR];
    __shared__ float  rt[KW * Dd];     // relT[j][d]

    const int b   = blockIdx.z;
    const int g   = blockIdx.y;
    const int s0  = blockIdx.x * TSs;
    const int tid = threadIdx.x;
    const int lane = tid & 31, warp = tid >> 5;
    const int sub  = lane >> 3;               // 0..3
    const int sidx = warp * 8 + (lane & 7);   // 0..63
    const int s    = s0 + sidx;
    const int m    = b * Ss + s;

    for (int i = tid; i < RROWS * 16; i += 256) {
        const int r = i >> 4, c = (i & 15) * 4;
        const int gr = s0 - PADK + r;
        float* kd = &ks[r * KSTR + c];
        if (gr >= 0 && gr < Ss) {
            cp_async16(kd, &g_k[((size_t)(b * Ss + gr)) * FOUT + g * Dd + c]);
        } else {
            *(float4*)kd = make_float4(0.f, 0.f, 0.f, 0.f);
        }
    }
    for (int i = tid; i < RROWS * 8; i += 256) {
        const int r = i >> 3, c = (i & 7) * 8;   // c in halves
        const int gr = s0 - PADK + r;
        __half* vd = &vs[r * VSTR + c];
        if (gr >= 0 && gr < Ss) {
            cp_async16(vd, &g_vh[((size_t)(b * Ss + gr)) * FOUT + g * Dd + c]);
        } else {
            *(uint4*)vd = make_uint4(0u, 0u, 0u, 0u);
        }
    }
    {
        const float* rsrc = rel + (size_t)g * Dd * KW;
        for (int i = tid; i < (Dd * KW) / 4; i += 256) {
            float4 v4 = *(const float4*)(rsrc + i * 4);
            float vv[4] = {v4.x, v4.y, v4.z, v4.w};
#pragma unroll
            for (int u = 0; u < 4; u++) {
                const int f = i * 4 + u;
                const int d = f / KW, j = f % KW;
                rt[j * Dd + d] = vv[u];
            }
        }
    }
    cp_commit();
    cp_wait0();
    __syncthreads();

    float4 q4[4];
    {
        const float* qp = &g_q[(size_t)m * FOUT + g * Dd + sub * 16];
#pragma unroll
        for (int c4 = 0; c4 < 4; c4++) q4[c4] = *(const float4*)(qp + 4 * c4);
    }

    float e[KW];
#pragma unroll
    for (int j = 0; j < KW; j++) {
        const float* kr = &ks[(sidx + j) * KSTR + sub * 16];
        const float* rr = &rt[j * Dd + sub * 16];
        float a0 = 0.f, a1 = 0.f;
#pragma unroll
        for (int c4 = 0; c4 < 4; c4++) {
            float4 kv = *(const float4*)(kr + 4 * c4);
            float4 rv = *(const float4*)(rr + 4 * c4);
            a0 = fmaf(q4[c4].x, kv.x + rv.x, a0);
            a1 = fmaf(q4[c4].y, kv.y + rv.y, a1);
            a0 = fmaf(q4[c4].z, kv.z + rv.z, a0);
            a1 = fmaf(q4[c4].w, kv.w + rv.w, a1);
        }
        float acc = a0 + a1;
        acc += __shfl_xor_sync(0xffffffffu, acc, 8);
        acc += __shfl_xor_sync(0xffffffffu, acc, 16);
        e[j] = acc;
    }

    float mx = e[0];
#pragma unroll
    for (int j = 1; j < KW; j++) mx = fmaxf(mx, e[j]);
    float sum = 0.f;
#pragma unroll
    for (int j = 0; j < KW; j++) { e[j] = __expf(e[j] - mx); sum += e[j]; }
    const float inv = 1.f / sum;
#pragma unroll
    for (int j = 0; j < KW; j++) e[j] *= inv;

    {
        float* ap = &attn_out[((size_t)m * Gg + g) * KW];
#pragma unroll
        for (int u = 0; u < 4; u++) {
            const int j = sub * 4 + u;
            float val = (j == 0) ? e[0] : (j == 1) ? e[1] : (j == 2) ? e[2] :
                        (j == 3) ? e[3] : (j == 4) ? e[4] : (j == 5) ? e[5] :
                        (j == 6) ? e[6] : (j == 7) ? e[7] : (j == 8) ? e[8] :
                        (j == 9) ? e[9] : (j == 10) ? e[10] : (j == 11) ? e[11] :
                        (j == 12) ? e[12] : (j == 13) ? e[13] : (j == 14) ? e[14] : e[15];
            ap[j] = val;
        }
        if (sub == 0) ap[16] = e[16];
    }

    float o[16];
#pragma unroll
    for (int u = 0; u < 16; u++) o[u] = 0.f;
#pragma unroll
    for (int j = 0; j < KW; j++) {
        const __half* vr = &vs[(sidx + j) * VSTR + sub * 16];
        uint4 p0 = *(const uint4*)vr;        // halves 0..7
        uint4 p1 = *(const uint4*)(vr + 8);  // halves 8..15
        uint32_t pw[8] = {p0.x, p0.y, p0.z, p0.w, p1.x, p1.y, p1.z, p1.w};
        const float w = e[j];
#pragma unroll
        for (int u = 0; u < 8; u++) {
            float2 f = __half22float2(*(const __half2*)&pw[u]);
            o[2 * u]     = fmaf(w, f.x, o[2 * u]);
            o[2 * u + 1] = fmaf(w, f.y, o[2 * u + 1]);
        }
    }
    {
        float* op = &out[(size_t)m * FOUT + g * Dd + sub * 16];
#pragma unroll
        for (int c4 = 0; c4 < 4; c4++)
            *(float4*)(op + 4 * c4) =
                make_float4(o[4*c4], o[4*c4+1], o[4*c4+2], o[4*c4+3]);
    }
}

// ---------------------------------------------------------------------------
extern "C" void kernel_launch(void* const* d_in, const int* in_sizes, int n_in,
                              void* d_out, int out_size)
{
    const float* x   = (const float*)d_in[0];
    const float* Wq  = (const float*)d_in[1];
    const float* Wk  = (const float*)d_in[2];
    const float* Wv  = (const float*)d_in[3];
    const float* rel = (const float*)d_in[4];

    float* out  = (float*)d_out;
    float* attn = out + (size_t)Mrows * FOUT;

    const int nsplit = (int)((XN4 + 3 * WN4) / 256);
    split_all<<<nsplit, 256>>>(x, Wq, Wk, Wv);

    gemm_all<<<296, 256>>>();

    dim3 ga(Ss / TSs, Gg, Bb);
    attn2<<<ga, 256>>>(rel, out, attn);
}